// round 2
// baseline (speedup 1.0000x reference)
#include <cuda_runtime.h>
#include <math.h>

// Problem constants
#define BTOT 131072
#define DIN  768
#define DHID 256
#define DOUT 64
#define NCAT 320            // DHID + DOUT (fused [W1;Wr])
#define NBLK 2048           // BTOT / 64 row-blocks

// ---------------- scratch (device globals; no runtime alloc) ----------------
__device__ float g_X[(size_t)BTOT * DOUT];                 // h_orth, 33.5 MB
__device__ float g_psum[NBLK * DOUT];                      // per-block column sums
__device__ float g_pcov[(size_t)NBLK * DOUT * DOUT];       // per-block X^T X partials
__device__ float g_pcov2[32 * DOUT * DOUT];                // stage-2 reduction
__device__ float g_Cv[DOUT * DOUT];                        // (Wv @ W)/sqrt(sn)
__device__ float g_Cm[DOUT * DOUT];                        // (Wm @ W)/sqrt(sn)
__device__ float g_bv2[DOUT];                              // bv - mu @ Cv^T
__device__ float g_bm2[DOUT];                              // bm - mu @ Cm^T

// smem float counts
#define SMEM1_FLOATS (64 * 257 + 2 * 64 * 65)   // hs + rs + hl (stage1 zs/ws fits inside)
#define SMEM2_FLOATS (4 * 64 * 65)
#define SMEM3_FLOATS (64 * 65 + 2 * 64 * 65)

// =====================================================================
// Kernel 1: per 64-row block:
//   g = z @ [W1;Wr]^T  (one pass over z, N=320)
//   h = GELU(LN(g[:, :256] + b1))
//   hl = h @ W2^T + b2 + (g[:, 256:] + br)
//   X  = hl @ Wo^T   -> g_X, plus partial col-sums and X^T X
// =====================================================================
__global__ void k1_main(const float* __restrict__ z,  const float* __restrict__ W1,
                        const float* __restrict__ b1, const float* __restrict__ lng,
                        const float* __restrict__ lnb, const float* __restrict__ W2,
                        const float* __restrict__ b2, const float* __restrict__ Wr,
                        const float* __restrict__ br, const float* __restrict__ Wo)
{
    extern __shared__ float sm[];
    float* zs = sm;                 // [64][33]  (stage 1 only)
    float* ws = sm + 64 * 33;       // [320][33] (stage 1 only)
    float* hs = sm;                 // [64][257]
    float* rs = sm + 64 * 257;      // [64][65]
    float* hl = rs + 64 * 65;       // [64][65]
    float* os = sm;                 // [64][65], aliases hs (dead by then)

    const int tid = threadIdx.x;
    const int tx = tid & 15, ty = tid >> 4;
    const int m0 = blockIdx.x * 64;

    float acc[4][20];
    #pragma unroll
    for (int i = 0; i < 4; i++)
        #pragma unroll
        for (int j = 0; j < 20; j++) acc[i][j] = 0.f;

    // ---- big GEMM: 64 x 320 x 768, K-chunks of 32 ----
    for (int kk = 0; kk < DIN; kk += 32) {
        #pragma unroll
        for (int t = 0; t < 8; t++) {           // z tile 64x32
            int i = tid + t * 256;
            int row = i >> 5, c = i & 31;
            zs[row * 33 + c] = z[(size_t)(m0 + row) * DIN + kk + c];
        }
        #pragma unroll
        for (int t = 0; t < 40; t++) {          // W tile 320x32
            int i = tid + t * 256;
            int row = i >> 5, c = i & 31;
            const float* srcp = (row < 256) ? (W1 + (size_t)row * DIN)
                                            : (Wr + (size_t)(row - 256) * DIN);
            ws[row * 33 + c] = srcp[kk + c];
        }
        __syncthreads();
        #pragma unroll 8
        for (int k = 0; k < 32; k++) {
            float a[4], bb[20];
            #pragma unroll
            for (int i = 0; i < 4; i++) a[i] = zs[(ty * 4 + i) * 33 + k];
            #pragma unroll
            for (int j = 0; j < 20; j++) bb[j] = ws[(tx + 16 * j) * 33 + k];
            #pragma unroll
            for (int i = 0; i < 4; i++)
                #pragma unroll
                for (int j = 0; j < 20; j++) acc[i][j] += a[i] * bb[j];
        }
        __syncthreads();
    }

    // ---- scatter accumulators + biases into hs / rs ----
    #pragma unroll
    for (int i = 0; i < 4; i++) {
        int row = ty * 4 + i;
        #pragma unroll
        for (int j = 0; j < 20; j++) {
            int col = tx + 16 * j;              // 0..319
            if (col < 256) hs[row * 257 + col] = acc[i][j] + b1[col];
            else           rs[row * 65 + (col - 256)] = acc[i][j] + br[col - 256];
        }
    }
    __syncthreads();

    // ---- LayerNorm + exact GELU, one warp per row ----
    {
        int lane = tid & 31, w = tid >> 5;
        for (int r = w; r < 64; r += 8) {
            float v[8]; float s = 0.f, s2 = 0.f;
            #pragma unroll
            for (int jj = 0; jj < 8; jj++) {
                float x = hs[r * 257 + lane + 32 * jj];
                v[jj] = x; s += x; s2 += x * x;
            }
            #pragma unroll
            for (int o = 16; o > 0; o >>= 1) {
                s  += __shfl_xor_sync(0xffffffffu, s,  o);
                s2 += __shfl_xor_sync(0xffffffffu, s2, o);
            }
            float mean = s * (1.f / 256.f);
            float var  = s2 * (1.f / 256.f) - mean * mean;
            float rstd = rsqrtf(var + 1e-5f);
            #pragma unroll
            for (int jj = 0; jj < 8; jj++) {
                int c = lane + 32 * jj;
                float y = (v[jj] - mean) * rstd * lng[c] + lnb[c];
                hs[r * 257 + c] = 0.5f * y * (1.0f + erff(y * 0.70710678118654752f));
            }
        }
    }
    __syncthreads();

    // ---- hl = hs @ W2^T + b2 + rs   (64x64, K=256) ----
    {
        int j = tid & 63, rg = tid >> 6;
        float a2[16];
        #pragma unroll
        for (int i = 0; i < 16; i++) a2[i] = 0.f;
        #pragma unroll 4
        for (int k = 0; k < 256; k++) {
            float wv = __ldg(&W2[j * 256 + k]);
            #pragma unroll
            for (int i = 0; i < 16; i++) a2[i] += hs[(rg * 16 + i) * 257 + k] * wv;
        }
        #pragma unroll
        for (int i = 0; i < 16; i++) {
            int row = rg * 16 + i;
            hl[row * 65 + j] = a2[i] + b2[j] + rs[row * 65 + j];
        }
    }
    __syncthreads();

    // ---- os = hl @ Wo^T   (64x64, K=64), os aliases hs (dead) ----
    {
        int j = tid & 63, rg = tid >> 6;
        float a2[16];
        #pragma unroll
        for (int i = 0; i < 16; i++) a2[i] = 0.f;
        #pragma unroll 4
        for (int k = 0; k < 64; k++) {
            float wv = __ldg(&Wo[j * 64 + k]);
            #pragma unroll
            for (int i = 0; i < 16; i++) a2[i] += hl[(rg * 16 + i) * 65 + k] * wv;
        }
        #pragma unroll
        for (int i = 0; i < 16; i++) os[(rg * 16 + i) * 65 + j] = a2[i];
    }
    __syncthreads();

    // ---- write X, partial column-sums, partial X^T X ----
    for (int i = tid; i < 4096; i += 256) {
        int row = i >> 6, j = i & 63;
        g_X[(size_t)(m0 + row) * 64 + j] = os[row * 65 + j];
    }
    if (tid < 64) {
        float s = 0.f;
        #pragma unroll 8
        for (int r = 0; r < 64; r++) s += os[r * 65 + tid];
        g_psum[blockIdx.x * 64 + tid] = s;
    }
    {
        int j2 = tid & 63, g = tid >> 6;
        #pragma unroll
        for (int i = 0; i < 16; i++) {
            int j1 = g * 16 + i;
            float s = 0.f;
            #pragma unroll 8
            for (int r = 0; r < 64; r++) s += os[r * 65 + j1] * os[r * 65 + j2];
            g_pcov[(size_t)blockIdx.x * 4096 + j1 * 64 + j2] = s;
        }
    }
}

// =====================================================================
// Kernel R: deterministic tree reduce of g_pcov: 2048 -> 32 partials
// =====================================================================
__global__ void k_red()
{
    int gt = blockIdx.x * 256 + threadIdx.x;   // 0 .. 131071
    int e = gt & 4095, ch = gt >> 12;          // ch in 0..31
    const float* p = g_pcov + (size_t)ch * 64 * 4096 + e;
    float s = 0.f;
    #pragma unroll 8
    for (int b = 0; b < 64; b++) s += p[(size_t)b * 4096];
    g_pcov2[ch * 4096 + e] = s;
}

// =====================================================================
// Kernel 2 (1 block): mu, sigma, Newton-Schulz (5 iters), fold into
// Cv=(Wv@W)/sqrt(sn), Cm=(Wm@W)/sqrt(sn), bv2, bm2.
// =====================================================================
__global__ void k2_ns(const float* __restrict__ Wv, const float* __restrict__ bv,
                      const float* __restrict__ Wm, const float* __restrict__ bm)
{
    extern __shared__ float sm[];
    float* Ss = sm;                 // sigma_scaled [64][65]
    float* Wp = sm + 4160;          // W iterate
    float* T1 = sm + 8320;
    float* T2 = sm + 12480;
    __shared__ float mu[64];
    __shared__ float snorm_s;

    const int tid = threadIdx.x;
    const float Bf = (float)BTOT;

    // mu
    {
        int col = tid & 63, q = tid >> 6;
        float s = 0.f;
        for (int b = q; b < NBLK; b += 4) s += g_psum[b * 64 + col];
        T1[q * 64 + col] = s;
        __syncthreads();
        if (tid < 64)
            mu[tid] = (T1[tid] + T1[64 + tid] + T1[128 + tid] + T1[192 + tid]) / Bf;
        __syncthreads();
    }
    // raw sigma into T2
    for (int i = tid; i < 4096; i += 256) {
        int j1 = i >> 6, j2 = i & 63;
        float c = 0.f;
        #pragma unroll 8
        for (int ch = 0; ch < 32; ch++) c += g_pcov2[ch * 4096 + i];
        float sig = (c - Bf * mu[j1] * mu[j2]) / (Bf - 1.0f);
        if (j1 == j2) sig += 0.001f;
        T2[j1 * 65 + j2] = sig;
    }
    __syncthreads();
    // trace -> sigma_norm
    if (tid < 32) {
        float t = T2[tid * 65 + tid] + T2[(tid + 32) * 65 + (tid + 32)];
        #pragma unroll
        for (int o = 16; o > 0; o >>= 1) t += __shfl_xor_sync(0xffffffffu, t, o);
        if (tid == 0) snorm_s = t * 1.5f + 1e-6f;
    }
    __syncthreads();
    float snorm = snorm_s;
    for (int i = tid; i < 4096; i += 256) {
        int j1 = i >> 6, j2 = i & 63;
        Ss[j1 * 65 + j2] = T2[j1 * 65 + j2] / snorm;
        Wp[j1 * 65 + j2] = (j1 == j2) ? 1.f : 0.f;
    }
    __syncthreads();

    const int j = tid & 63, rg = tid >> 6;
    for (int it = 0; it < 5; it++) {
        // T1 = W @ Ss
        #pragma unroll
        for (int i = 0; i < 16; i++) {
            int r = rg * 16 + i; float s = 0.f;
            #pragma unroll 8
            for (int k = 0; k < 64; k++) s += Wp[r * 65 + k] * Ss[k * 65 + j];
            T1[r * 65 + j] = s;
        }
        __syncthreads();
        // T2 = T1 @ W^T   (= P)
        #pragma unroll
        for (int i = 0; i < 16; i++) {
            int r = rg * 16 + i; float s = 0.f;
            #pragma unroll 8
            for (int k = 0; k < 64; k++) s += T1[r * 65 + k] * Wp[j * 65 + k];
            T2[r * 65 + j] = s;
        }
        __syncthreads();
        // T1 = 1.5 W - 0.5 (P @ W)
        #pragma unroll
        for (int i = 0; i < 16; i++) {
            int r = rg * 16 + i; float s = 0.f;
            #pragma unroll 8
            for (int k = 0; k < 64; k++) s += T2[r * 65 + k] * Wp[k * 65 + j];
            T1[r * 65 + j] = 1.5f * Wp[r * 65 + j] - 0.5f * s;
        }
        __syncthreads();
        for (int i = tid; i < 4160; i += 256) Wp[i] = T1[i];
        __syncthreads();
    }

    float iss = rsqrtf(snorm);
    // Cv = (Wv @ W) * iss  -> T1 & g_Cv
    {
        int kcol = tid & 63, jg = tid >> 6;
        #pragma unroll
        for (int i = 0; i < 16; i++) {
            int jr = jg * 16 + i; float s = 0.f;
            #pragma unroll 8
            for (int d = 0; d < 64; d++) s += __ldg(&Wv[jr * 64 + d]) * Wp[d * 65 + kcol];
            float c = s * iss;
            T1[jr * 65 + kcol] = c;
            g_Cv[jr * 64 + kcol] = c;
        }
    }
    __syncthreads();
    if (tid < 64) {
        float s = 0.f;
        #pragma unroll 8
        for (int k = 0; k < 64; k++) s += mu[k] * T1[tid * 65 + k];
        g_bv2[tid] = bv[tid] - s;
    }
    // Cm = (Wm @ W) * iss -> T2 & g_Cm
    {
        int kcol = tid & 63, jg = tid >> 6;
        #pragma unroll
        for (int i = 0; i < 16; i++) {
            int jr = jg * 16 + i; float s = 0.f;
            #pragma unroll 8
            for (int d = 0; d < 64; d++) s += __ldg(&Wm[jr * 64 + d]) * Wp[d * 65 + kcol];
            float c = s * iss;
            T2[jr * 65 + kcol] = c;
            g_Cm[jr * 64 + kcol] = c;
        }
    }
    __syncthreads();
    if (tid < 64) {
        float s = 0.f;
        #pragma unroll 8
        for (int k = 0; k < 64; k++) s += mu[k] * T2[tid * 65 + k];
        g_bm2[tid] = bm[tid] - s;
    }
}

// =====================================================================
// Kernel 3: out = (X @ Cv^T + bv2) * sigmoid(X @ Cm^T + bm2) * scale
// =====================================================================
__global__ void k3_out(float* __restrict__ out, const float* __restrict__ scale)
{
    extern __shared__ float sm[];
    float* Xs  = sm;            // [64][65]
    float* Cvs = sm + 4160;     // [64][65]
    float* Cms = sm + 8320;     // [64][65]
    const int tid = threadIdx.x;
    const int m0 = blockIdx.x * 64;

    for (int i = tid; i < 4096; i += 256) {
        int row = i >> 6, j = i & 63;
        Xs[row * 65 + j]  = g_X[(size_t)(m0 + row) * 64 + j];
        Cvs[row * 65 + j] = g_Cv[i];
        Cms[row * 65 + j] = g_Cm[i];
    }
    __syncthreads();

    const int j = tid & 63, rg = tid >> 6;
    const float bv2 = g_bv2[j], bm2 = g_bm2[j], sc = scale[0];
    #pragma unroll
    for (int i = 0; i < 16; i++) {
        int row = rg * 16 + i;
        float av = 0.f, am = 0.f;
        #pragma unroll 8
        for (int k = 0; k < 64; k++) {
            float x = Xs[row * 65 + k];
            av += x * Cvs[j * 65 + k];
            am += x * Cms[j * 65 + k];
        }
        float m = 1.f / (1.f + expf(-(am + bm2)));
        out[(size_t)(m0 + row) * 64 + j] = (av + bv2) * m * sc;
    }
}

// =====================================================================
extern "C" void kernel_launch(void* const* d_in, const int* in_sizes, int n_in,
                              void* d_out, int out_size)
{
    (void)in_sizes; (void)n_in; (void)out_size;
    const float* z    = (const float*)d_in[0];
    const float* W1   = (const float*)d_in[1];
    const float* b1   = (const float*)d_in[2];
    const float* ln_g = (const float*)d_in[3];
    const float* ln_b = (const float*)d_in[4];
    const float* W2   = (const float*)d_in[5];
    const float* b2   = (const float*)d_in[6];
    const float* Wr   = (const float*)d_in[7];
    const float* br   = (const float*)d_in[8];
    const float* Wo   = (const float*)d_in[9];
    const float* Wv   = (const float*)d_in[10];
    const float* bv   = (const float*)d_in[11];
    const float* Wm   = (const float*)d_in[12];
    const float* bm   = (const float*)d_in[13];
    const float* scale = (const float*)d_in[14];
    float* out = (float*)d_out;

    const int smem1 = SMEM1_FLOATS * 4;
    const int smem2 = SMEM2_FLOATS * 4;
    const int smem3 = SMEM3_FLOATS * 4;
    cudaFuncSetAttribute(k1_main, cudaFuncAttributeMaxDynamicSharedMemorySize, smem1);
    cudaFuncSetAttribute(k2_ns,   cudaFuncAttributeMaxDynamicSharedMemorySize, smem2);
    cudaFuncSetAttribute(k3_out,  cudaFuncAttributeMaxDynamicSharedMemorySize, smem3);

    k1_main<<<NBLK, 256, smem1>>>(z, W1, b1, ln_g, ln_b, W2, b2, Wr, br, Wo);
    k_red<<<512, 256>>>();
    k2_ns<<<1, 256, smem2>>>(Wv, bv, Wm, bm);
    k3_out<<<NBLK, 256, smem3>>>(out, scale);
}

// round 5
// speedup vs baseline: 2.1487x; 2.1487x over previous
#include <cuda_runtime.h>
#include <cuda_bf16.h>
#include <math.h>
#include <stdint.h>

#define BTOT 131072
#define DIN  768
#define NBLK 2048            // BTOT / 64 rows per CTA

extern __shared__ char dsm[];

// ---------- tensor-core helpers (portable mma.sync path) ----------
__device__ __forceinline__ uint32_t smem_u32(const void* p) {
    uint32_t a;
    asm("{ .reg .u64 t; cvta.to.shared.u64 t, %1; cvt.u32.u64 %0, t; }" : "=r"(a) : "l"(p));
    return a;
}
#define LDSM4(r,a) asm volatile("ldmatrix.sync.aligned.m8n8.x4.shared.b16 {%0,%1,%2,%3},[%4];" \
    : "=r"((r)[0]),"=r"((r)[1]),"=r"((r)[2]),"=r"((r)[3]) : "r"(a))
#define LDSM2(r,a) asm volatile("ldmatrix.sync.aligned.m8n8.x2.shared.b16 {%0,%1},[%2];" \
    : "=r"((r)[0]),"=r"((r)[1]) : "r"(a))
#define MMA16816(c,a,b) asm volatile( \
    "mma.sync.aligned.m16n8k16.row.col.f32.bf16.bf16.f32 {%0,%1,%2,%3},{%4,%5,%6,%7},{%8,%9},{%0,%1,%2,%3};" \
    : "+f"((c)[0]),"+f"((c)[1]),"+f"((c)[2]),"+f"((c)[3]) \
    : "r"((a)[0]),"r"((a)[1]),"r"((a)[2]),"r"((a)[3]),"r"((b)[0]),"r"((b)[1]))

__device__ __forceinline__ void split2(float x0, float x1, uint32_t& h, uint32_t& l) {
    __nv_bfloat16 h0 = __float2bfloat16(x0), h1 = __float2bfloat16(x1);
    h = (uint32_t)__bfloat16_as_ushort(h0) | ((uint32_t)__bfloat16_as_ushort(h1) << 16);
    __nv_bfloat16 l0 = __float2bfloat16(x0 - __bfloat162float(h0));
    __nv_bfloat16 l1 = __float2bfloat16(x1 - __bfloat162float(h1));
    l = (uint32_t)__bfloat16_as_ushort(l0) | ((uint32_t)__bfloat16_as_ushort(l1) << 16);
}

// ---------- scratch ----------
__device__ float g_X[(size_t)BTOT * 64];
__device__ float g_psum[NBLK * 64];
__device__ float g_pcov[(size_t)NBLK * 4096];
__device__ float g_pcov2[32 * 4096];
__device__ float g_Cv[4096], g_Cm[4096], g_bv2[64], g_bm2[64];
__device__ __align__(16) __nv_bfloat16 g_Wch[320 * 768], g_Wcl[320 * 768];
__device__ __align__(16) __nv_bfloat16 g_W2h[64 * 256],  g_W2l[64 * 256];

// k1 smem byte layout
// GEMM1 tiles (phase 1): A_h/A_l [64][72]bf16, B_h/B_l [320][72]bf16
#define OA_H 0
#define OA_L 9216
#define OB_H 18432
#define OB_L 64512           // ends 110592
// float regions (phase 2+, alias tiles): hs [64][257] @0, rs @65792, hl @82432
#define F_HS 0
#define F_RS 16448           // float index
#define F_HL 20608           // float index
// W2 tiles (phase 3): behind hl
#define OA2_H 99072
#define OA2_L 108288
#define OB2_H 117504
#define OB2_L 126720
#define SM1   135936

__global__ void k0_prep(const float* __restrict__ W1, const float* __restrict__ Wr,
                        const float* __restrict__ W2) {
    int gt = blockIdx.x * 256 + threadIdx.x, np = gridDim.x * 256;
    for (int i = gt; i < 320 * 768; i += np) {
        int r = i / 768, c = i - r * 768;
        float v = (r < 256) ? W1[r * 768 + c] : Wr[(r - 256) * 768 + c];
        __nv_bfloat16 h = __float2bfloat16(v);
        g_Wch[i] = h; g_Wcl[i] = __float2bfloat16(v - __bfloat162float(h));
    }
    for (int i = gt; i < 64 * 256; i += np) {
        float v = W2[i]; __nv_bfloat16 h = __float2bfloat16(v);
        g_W2h[i] = h; g_W2l[i] = __float2bfloat16(v - __bfloat162float(h));
    }
}

__global__ void __launch_bounds__(256, 1)
k1_main(const float* __restrict__ z,  const float* __restrict__ b1,
        const float* __restrict__ lng, const float* __restrict__ lnb,
        const float* __restrict__ b2,  const float* __restrict__ br,
        const float* __restrict__ Wo)
{
    char* sm = dsm;
    const uint32_t sb = smem_u32(sm);
    float* smf = (float*)sm;
    float* hs = smf + F_HS;      // [64][257]
    float* rs = smf + F_RS;      // [64][65]
    float* hl = smf + F_HL;      // [64][65]
    float* os = smf + F_HS;      // [64][65], aliases hs (dead by then)

    const int tid = threadIdx.x, wid = tid >> 5, lane = tid & 31;
    const int m0 = blockIdx.x * 64;
    const int wr = wid & 3, wc = wid >> 2;          // warp grid 4 x 2
    const int g = lane >> 2, tig = lane & 3;

    // per-lane ldmatrix byte offsets (stride 144B rows)
    const uint32_t aoff = (uint32_t)((lane & 15)) * 144u + (uint32_t)((lane >> 4) * 16);
    const uint32_t boff = (uint32_t)((lane & 7)) * 144u + (uint32_t)(((lane >> 3) & 1) * 16);
    const uint32_t aRow = (uint32_t)(wr * 16) * 144u;

    // ================= GEMM1: 64 x 320 x 768, mma.sync bf16 hi/lo =================
    float acc[20][4];
    #pragma unroll
    for (int j = 0; j < 20; j++)
        #pragma unroll
        for (int q = 0; q < 4; q++) acc[j][q] = 0.f;

    for (int ch = 0; ch < 12; ch++) {
        const int kk = ch * 64;
        #pragma unroll
        for (int it = 0; it < 4; it++) {             // A: z 64x64 fp32 -> hi/lo
            int p = tid + it * 256, row = p >> 4, q = p & 15;
            float4 v = *(const float4*)(z + (size_t)(m0 + row) * 768 + kk + q * 4);
            uint32_t h01, l01, h23, l23;
            split2(v.x, v.y, h01, l01); split2(v.z, v.w, h23, l23);
            uint32_t off = (uint32_t)row * 144u + (uint32_t)q * 8u;
            *(uint2*)(sm + OA_H + off) = make_uint2(h01, h23);
            *(uint2*)(sm + OA_L + off) = make_uint2(l01, l23);
        }
        #pragma unroll
        for (int it = 0; it < 10; it++) {            // B: 320x64 bf16 hi/lo
            int p = tid + it * 256, row = p >> 3, c = p & 7;
            size_t si = (size_t)row * 768 + kk + c * 8;
            uint32_t off = (uint32_t)row * 144u + (uint32_t)c * 16u;
            *(uint4*)(sm + OB_H + off) = *(const uint4*)(g_Wch + si);
            *(uint4*)(sm + OB_L + off) = *(const uint4*)(g_Wcl + si);
        }
        __syncthreads();
        #pragma unroll
        for (int ks = 0; ks < 4; ks++) {
            const uint32_t ka = (uint32_t)ks * 32u;
            uint32_t ah[4], al[4];
            LDSM4(ah, sb + OA_H + aRow + aoff + ka);
            LDSM4(al, sb + OA_L + aRow + aoff + ka);
            #pragma unroll
            for (int j = 0; j < 20; j++) {
                uint32_t bo = (uint32_t)(wc * 160 + j * 8) * 144u + boff + ka;
                uint32_t bh[2], bl[2];
                LDSM2(bh, sb + OB_H + bo);
                LDSM2(bl, sb + OB_L + bo);
                MMA16816(acc[j], ah, bh);
                MMA16816(acc[j], al, bh);
                MMA16816(acc[j], ah, bl);
            }
        }
        __syncthreads();
    }

    // scatter acc -> hs (cols<256, +b1) / rs (cols>=256, +br)
    #pragma unroll
    for (int j = 0; j < 20; j++) {
        int col = wc * 160 + j * 8 + tig * 2;
        int r0 = wr * 16 + g, r1 = r0 + 8;
        #pragma unroll
        for (int e = 0; e < 2; e++) {
            int c = col + e;
            float v0 = acc[j][e], v1 = acc[j][2 + e];
            if (c < 256) {
                hs[r0 * 257 + c] = v0 + __ldg(&b1[c]);
                hs[r1 * 257 + c] = v1 + __ldg(&b1[c]);
            } else {
                rs[r0 * 65 + c - 256] = v0 + __ldg(&br[c - 256]);
                rs[r1 * 65 + c - 256] = v1 + __ldg(&br[c - 256]);
            }
        }
    }
    __syncthreads();

    // ================= LayerNorm + exact GELU =================
    for (int rr = wid; rr < 64; rr += 8) {
        float v[8], s = 0.f, s2 = 0.f;
        #pragma unroll
        for (int j = 0; j < 8; j++) {
            float x = hs[rr * 257 + lane + 32 * j];
            v[j] = x; s += x; s2 += x * x;
        }
        #pragma unroll
        for (int o = 16; o > 0; o >>= 1) {
            s  += __shfl_xor_sync(~0u, s,  o);
            s2 += __shfl_xor_sync(~0u, s2, o);
        }
        float mean = s * (1.f / 256.f);
        float rstd = rsqrtf(s2 * (1.f / 256.f) - mean * mean + 1e-5f);
        #pragma unroll
        for (int j = 0; j < 8; j++) {
            int c = lane + 32 * j;
            float y = (v[j] - mean) * rstd * __ldg(&lng[c]) + __ldg(&lnb[c]);
            hs[rr * 257 + c] = 0.5f * y * (1.0f + erff(y * 0.70710678118654752f));
        }
    }
    __syncthreads();

    // ================= W2 GEMM: 64 x 64 x 256, mma.sync =================
    float acc2[4][4];
    #pragma unroll
    for (int j = 0; j < 4; j++)
        #pragma unroll
        for (int q = 0; q < 4; q++) acc2[j][q] = 0.f;

    for (int c2 = 0; c2 < 4; c2++) {
        const int kk2 = c2 * 64;
        #pragma unroll
        for (int it = 0; it < 8; it++) {             // A2: GELU(h) chunk -> hi/lo
            int p = tid + it * 256, row = p >> 5, cp = p & 31;
            uint32_t h01, l01;
            split2(hs[row * 257 + kk2 + 2 * cp], hs[row * 257 + kk2 + 2 * cp + 1], h01, l01);
            uint32_t off = (uint32_t)row * 144u + (uint32_t)cp * 4u;
            *(uint32_t*)(sm + OA2_H + off) = h01;
            *(uint32_t*)(sm + OA2_L + off) = l01;
        }
        #pragma unroll
        for (int it = 0; it < 2; it++) {             // B2: W2 chunk 64x64
            int p = tid + it * 256, row = p >> 3, c = p & 7;
            size_t si = (size_t)row * 256 + kk2 + c * 8;
            uint32_t off = (uint32_t)row * 144u + (uint32_t)c * 16u;
            *(uint4*)(sm + OB2_H + off) = *(const uint4*)(g_W2h + si);
            *(uint4*)(sm + OB2_L + off) = *(const uint4*)(g_W2l + si);
        }
        __syncthreads();
        #pragma unroll
        for (int ks = 0; ks < 4; ks++) {
            const uint32_t ka = (uint32_t)ks * 32u;
            uint32_t ah[4], al[4];
            LDSM4(ah, sb + OA2_H + aRow + aoff + ka);
            LDSM4(al, sb + OA2_L + aRow + aoff + ka);
            #pragma unroll
            for (int j = 0; j < 4; j++) {
                uint32_t bo = (uint32_t)(wc * 32 + j * 8) * 144u + boff + ka;
                uint32_t bh[2], bl[2];
                LDSM2(bh, sb + OB2_H + bo);
                LDSM2(bl, sb + OB2_L + bo);
                MMA16816(acc2[j], ah, bh);
                MMA16816(acc2[j], al, bh);
                MMA16816(acc2[j], ah, bl);
            }
        }
        __syncthreads();
    }
    // hl = acc2 + b2 + rs
    #pragma unroll
    for (int j = 0; j < 4; j++) {
        int col = wc * 32 + j * 8 + tig * 2;
        int r0 = wr * 16 + g, r1 = r0 + 8;
        #pragma unroll
        for (int e = 0; e < 2; e++) {
            int c = col + e;
            hl[r0 * 65 + c] = acc2[j][e]     + __ldg(&b2[c]) + rs[r0 * 65 + c];
            hl[r1 * 65 + c] = acc2[j][2 + e] + __ldg(&b2[c]) + rs[r1 * 65 + c];
        }
    }
    __syncthreads();

    // ================= Wo GEMM (FFMA, small): os = hl @ Wo^T =================
    {
        int j = tid & 63, rg = tid >> 6;
        float a2[16];
        #pragma unroll
        for (int i = 0; i < 16; i++) a2[i] = 0.f;
        #pragma unroll 4
        for (int k = 0; k < 64; k++) {
            float wv = __ldg(&Wo[j * 64 + k]);
            #pragma unroll
            for (int i = 0; i < 16; i++) a2[i] += hl[(rg * 16 + i) * 65 + k] * wv;
        }
        __syncthreads();   // hs (aliased by os) fully read already
        #pragma unroll
        for (int i = 0; i < 16; i++) os[(rg * 16 + i) * 65 + j] = a2[i];
    }
    __syncthreads();

    // ================= outputs: X, psum, pcov =================
    for (int i = tid; i < 4096; i += 256) {
        int row = i >> 6, j = i & 63;
        g_X[(size_t)(m0 + row) * 64 + j] = os[row * 65 + j];
    }
    if (tid < 64) {
        float s = 0.f;
        #pragma unroll 8
        for (int rr = 0; rr < 64; rr++) s += os[rr * 65 + tid];
        g_psum[blockIdx.x * 64 + tid] = s;
    }
    {
        int j2 = tid & 63, gq = tid >> 6;
        #pragma unroll
        for (int i = 0; i < 16; i++) {
            int j1 = gq * 16 + i;
            float s = 0.f;
            #pragma unroll 8
            for (int rr = 0; rr < 64; rr++) s += os[rr * 65 + j1] * os[rr * 65 + j2];
            g_pcov[(size_t)blockIdx.x * 4096 + j1 * 64 + j2] = s;
        }
    }
}

__global__ void k_red() {
    int gt = blockIdx.x * 256 + threadIdx.x;
    int e = gt & 4095, ch = gt >> 12;
    const float* p = g_pcov + (size_t)ch * 64 * 4096 + e;
    float s = 0.f;
    #pragma unroll 8
    for (int b = 0; b < 64; b++) s += p[(size_t)b * 4096];
    g_pcov2[ch * 4096 + e] = s;
}

__global__ void k2_ns(const float* __restrict__ Wv, const float* __restrict__ bv,
                      const float* __restrict__ Wm, const float* __restrict__ bm)
{
    float* smf = (float*)dsm;
    float* Ss = smf; float* Wp = smf + 4160; float* T1 = smf + 8320; float* T2 = smf + 12480;
    __shared__ float mu[64]; __shared__ float sn_s;
    const int tid = threadIdx.x;
    const float Bf = (float)BTOT;
    {
        int col = tid & 63, q = tid >> 6; float s = 0.f;
        for (int b = q; b < NBLK; b += 4) s += g_psum[b * 64 + col];
        T1[q * 64 + col] = s;
        __syncthreads();
        if (tid < 64) mu[tid] = (T1[tid] + T1[64 + tid] + T1[128 + tid] + T1[192 + tid]) / Bf;
        __syncthreads();
    }
    for (int i = tid; i < 4096; i += 256) {
        int j1 = i >> 6, j2 = i & 63; float c = 0.f;
        #pragma unroll 8
        for (int ch = 0; ch < 32; ch++) c += g_pcov2[ch * 4096 + i];
        float sig = (c - Bf * mu[j1] * mu[j2]) / (Bf - 1.0f);
        if (j1 == j2) sig += 0.001f;
        T2[j1 * 65 + j2] = sig;
    }
    __syncthreads();
    if (tid < 32) {
        float t = T2[tid * 65 + tid] + T2[(tid + 32) * 65 + tid + 32];
        #pragma unroll
        for (int o = 16; o > 0; o >>= 1) t += __shfl_xor_sync(~0u, t, o);
        if (tid == 0) sn_s = t * 1.5f + 1e-6f;
    }
    __syncthreads();
    float sn = sn_s;
    for (int i = tid; i < 4096; i += 256) {
        int j1 = i >> 6, j2 = i & 63;
        Ss[j1 * 65 + j2] = T2[j1 * 65 + j2] / sn;
        Wp[j1 * 65 + j2] = (j1 == j2) ? 1.f : 0.f;
    }
    __syncthreads();
    const int j = tid & 63, rg = tid >> 6;
    for (int it = 0; it < 5; it++) {
        #pragma unroll
        for (int i = 0; i < 16; i++) {
            int rr = rg * 16 + i; float s = 0.f;
            #pragma unroll 8
            for (int k = 0; k < 64; k++) s += Wp[rr * 65 + k] * Ss[k * 65 + j];
            T1[rr * 65 + j] = s;
        }
        __syncthreads();
        #pragma unroll
        for (int i = 0; i < 16; i++) {
            int rr = rg * 16 + i; float s = 0.f;
            #pragma unroll 8
            for (int k = 0; k < 64; k++) s += T1[rr * 65 + k] * Wp[j * 65 + k];
            T2[rr * 65 + j] = s;
        }
        __syncthreads();
        #pragma unroll
        for (int i = 0; i < 16; i++) {
            int rr = rg * 16 + i; float s = 0.f;
            #pragma unroll 8
            for (int k = 0; k < 64; k++) s += T2[rr * 65 + k] * Wp[k * 65 + j];
            T1[rr * 65 + j] = 1.5f * Wp[rr * 65 + j] - 0.5f * s;
        }
        __syncthreads();
        for (int i = tid; i < 4160; i += 256) Wp[i] = T1[i];
        __syncthreads();
    }
    float iss = rsqrtf(sn);
    {
        int kc = tid & 63, jg = tid >> 6;
        #pragma unroll
        for (int i = 0; i < 16; i++) {
            int jr = jg * 16 + i; float s = 0.f, t = 0.f;
            #pragma unroll 8
            for (int d = 0; d < 64; d++) {
                s += __ldg(&Wv[jr * 64 + d]) * Wp[d * 65 + kc];
                t += __ldg(&Wm[jr * 64 + d]) * Wp[d * 65 + kc];
            }
            T1[jr * 65 + kc] = s * iss; g_Cv[jr * 64 + kc] = s * iss;
            T2[jr * 65 + kc] = t * iss; g_Cm[jr * 64 + kc] = t * iss;
        }
    }
    __syncthreads();
    if (tid < 64) {
        float s = 0.f, t = 0.f;
        #pragma unroll 8
        for (int k = 0; k < 64; k++) { s += mu[k] * T1[tid * 65 + k]; t += mu[k] * T2[tid * 65 + k]; }
        g_bv2[tid] = bv[tid] - s;
        g_bm2[tid] = bm[tid] - t;
    }
}

__global__ void k3_out(float* __restrict__ out, const float* __restrict__ scale)
{
    float* smf = (float*)dsm;
    float* Xs = smf; float* Cvs = smf + 4160; float* Cms = smf + 8320;
    const int tid = threadIdx.x, m0 = blockIdx.x * 64;
    for (int i = tid; i < 4096; i += 256) {
        int row = i >> 6, j = i & 63;
        Xs[row * 65 + j]  = g_X[(size_t)(m0 + row) * 64 + j];
        Cvs[row * 65 + j] = g_Cv[i];
        Cms[row * 65 + j] = g_Cm[i];
    }
    __syncthreads();
    const int j = tid & 63, rg = tid >> 6;
    const float bv2 = g_bv2[j], bm2 = g_bm2[j], sc = scale[0];
    #pragma unroll
    for (int i = 0; i < 16; i++) {
        int row = rg * 16 + i; float av = 0.f, am = 0.f;
        #pragma unroll 8
        for (int k = 0; k < 64; k++) {
            float x = Xs[row * 65 + k];
            av += x * Cvs[j * 65 + k];
            am += x * Cms[j * 65 + k];
        }
        float m = 1.f / (1.f + expf(-(am + bm2)));
        out[(size_t)(m0 + row) * 64 + j] = (av + bv2) * m * sc;
    }
}

extern "C" void kernel_launch(void* const* d_in, const int* in_sizes, int n_in,
                              void* d_out, int out_size)
{
    (void)in_sizes; (void)n_in; (void)out_size;
    const float* z  = (const float*)d_in[0];
    const float* W1 = (const float*)d_in[1];
    const float* b1 = (const float*)d_in[2];
    const float* lg = (const float*)d_in[3];
    const float* lb = (const float*)d_in[4];
    const float* W2 = (const float*)d_in[5];
    const float* b2 = (const float*)d_in[6];
    const float* Wr = (const float*)d_in[7];
    const float* br = (const float*)d_in[8];
    const float* Wo = (const float*)d_in[9];
    const float* Wv = (const float*)d_in[10];
    const float* bv = (const float*)d_in[11];
    const float* Wm = (const float*)d_in[12];
    const float* bm = (const float*)d_in[13];
    const float* sc = (const float*)d_in[14];
    float* out = (float*)d_out;

    cudaFuncSetAttribute(k1_main, cudaFuncAttributeMaxDynamicSharedMemorySize, SM1);
    cudaFuncSetAttribute(k2_ns,  cudaFuncAttributeMaxDynamicSharedMemorySize, 16640 * 4);
    cudaFuncSetAttribute(k3_out, cudaFuncAttributeMaxDynamicSharedMemorySize, 12480 * 4);

    k0_prep<<<256, 256>>>(W1, Wr, W2);
    k1_main<<<NBLK, 256, SM1>>>(z, b1, lg, lb, b2, br, Wo);
    k_red<<<512, 256>>>();
    k2_ns<<<1, 256, 16640 * 4>>>(Wv, bv, Wm, bm);
    k3_out<<<2048, 256, 12480 * 4>>>(out, sc);
}

// round 6
// speedup vs baseline: 3.3191x; 1.5447x over previous
#include <cuda_runtime.h>
#include <cuda_bf16.h>
#include <math.h>
#include <stdint.h>

#define BTOT 131072
#define NBLK 2048            // BTOT / 64 rows per CTA

extern __shared__ char dsm[];

// ---------- helpers ----------
__device__ __forceinline__ uint32_t smem_u32(const void* p) {
    uint32_t a;
    asm("{ .reg .u64 t; cvta.to.shared.u64 t, %1; cvt.u32.u64 %0, t; }" : "=r"(a) : "l"(p));
    return a;
}
#define LDSM4(r,a) asm volatile("ldmatrix.sync.aligned.m8n8.x4.shared.b16 {%0,%1,%2,%3},[%4];" \
    : "=r"((r)[0]),"=r"((r)[1]),"=r"((r)[2]),"=r"((r)[3]) : "r"(a))
#define LDSM2(r,a) asm volatile("ldmatrix.sync.aligned.m8n8.x2.shared.b16 {%0,%1},[%2];" \
    : "=r"((r)[0]),"=r"((r)[1]) : "r"(a))
#define MMA16816(c,a,b) asm volatile( \
    "mma.sync.aligned.m16n8k16.row.col.f32.bf16.bf16.f32 {%0,%1,%2,%3},{%4,%5,%6,%7},{%8,%9},{%0,%1,%2,%3};" \
    : "+f"((c)[0]),"+f"((c)[1]),"+f"((c)[2]),"+f"((c)[3]) \
    : "r"((a)[0]),"r"((a)[1]),"r"((a)[2]),"r"((a)[3]),"r"((b)[0]),"r"((b)[1]))
#define CP16(dst,src) asm volatile("cp.async.cg.shared.global [%0], [%1], 16;" ::"r"(dst),"l"(src))
#define CPCOMMIT()    asm volatile("cp.async.commit_group;" ::: "memory")
#define CPWAIT0()     asm volatile("cp.async.wait_group 0;" ::: "memory")

__device__ __forceinline__ void split2(float x0, float x1, uint32_t& h, uint32_t& l) {
    __nv_bfloat16 h0 = __float2bfloat16(x0), h1 = __float2bfloat16(x1);
    h = (uint32_t)__bfloat16_as_ushort(h0) | ((uint32_t)__bfloat16_as_ushort(h1) << 16);
    __nv_bfloat16 l0 = __float2bfloat16(x0 - __bfloat162float(h0));
    __nv_bfloat16 l1 = __float2bfloat16(x1 - __bfloat162float(h1));
    l = (uint32_t)__bfloat16_as_ushort(l0) | ((uint32_t)__bfloat16_as_ushort(l1) << 16);
}
// K=32 tile: 64B rows, rotation swizzle -> conflict-free ldmatrix
__device__ __forceinline__ uint32_t off32(uint32_t row, uint32_t c16) {
    return row * 64u + (((c16 + (row >> 1)) & 3u) << 4);
}

// ---------- scratch ----------
__device__ float g_X[(size_t)BTOT * 64];
__device__ float g_psum[NBLK * 64];
__device__ float g_pcov[(size_t)NBLK * 4096];
__device__ float g_pcov2[32 * 4096];
__device__ float g_Cv[4096], g_Cm[4096], g_bv2[64], g_bm2[64];
__device__ __align__(16) __nv_bfloat16 g_Wch[320 * 768], g_Wcl[320 * 768];
__device__ __align__(16) __nv_bfloat16 g_W2h[64 * 256],  g_W2l[64 * 256];
__device__ __align__(16) __nv_bfloat16 g_Woh[64 * 64],   g_Wol[64 * 64];

// k1 smem layout (bytes)
// GEMM1: A tiles 4KB each (h/l x 2 buf), B tiles 20480 each
#define G1_A(buf)  ((buf) * 8192)
#define G1_AL(buf) ((buf) * 8192 + 4096)
#define G1_B(buf)  (16384 + (buf) * 40960)
#define G1_BL(buf) (16384 + (buf) * 40960 + 20480)
// float regions (alias GEMM1 tiles after GEMM1 done)
#define F_HS 0               // hs [64][257] floats
#define F_RS 16448           // rs [64][65]  (float index)
#define F_HL 20608           // hl [64][65]  (float index)
// 144-stride tiles for W2 / Wo / Xt
#define OA2_H 99072
#define OA2_L 108288
#define OB2_H 117504
#define OB2_L 126720
#define SM1   135936

__global__ void k0_prep(const float* __restrict__ W1, const float* __restrict__ Wr,
                        const float* __restrict__ W2, const float* __restrict__ Wo) {
    int gt = blockIdx.x * 256 + threadIdx.x, np = gridDim.x * 256;
    for (int i = gt; i < 320 * 768; i += np) {
        int r = i / 768, c = i - r * 768;
        float v = (r < 256) ? W1[r * 768 + c] : Wr[(r - 256) * 768 + c];
        __nv_bfloat16 h = __float2bfloat16(v);
        g_Wch[i] = h; g_Wcl[i] = __float2bfloat16(v - __bfloat162float(h));
    }
    for (int i = gt; i < 64 * 256; i += np) {
        float v = W2[i]; __nv_bfloat16 h = __float2bfloat16(v);
        g_W2h[i] = h; g_W2l[i] = __float2bfloat16(v - __bfloat162float(h));
    }
    for (int i = gt; i < 4096; i += np) {
        float v = Wo[i]; __nv_bfloat16 h = __float2bfloat16(v);
        g_Woh[i] = h; g_Wol[i] = __float2bfloat16(v - __bfloat162float(h));
    }
}

__global__ void __launch_bounds__(256, 1)
k1_main(const float* __restrict__ z,  const float* __restrict__ b1,
        const float* __restrict__ lng, const float* __restrict__ lnb,
        const float* __restrict__ b2,  const float* __restrict__ br)
{
    char* sm = dsm;
    const uint32_t sb = smem_u32(sm);
    float* smf = (float*)sm;
    float* hs = smf + F_HS;      // [64][257]
    float* rs = smf + F_RS;      // [64][65]
    float* hl = smf + F_HL;      // [64][65]
    float* os = smf + F_HS;      // [64][65], aliases hs

    const int tid = threadIdx.x, wid = tid >> 5, lane = tid & 31;
    const int m0 = blockIdx.x * 64;
    const int wr = wid & 3, wc = wid >> 2;          // 4 x 2 warp grid
    const int g = lane >> 2, tig = lane & 3;

    // 144-stride ldmatrix lane offsets (W2/Wo/cov)
    const uint32_t aoff = (uint32_t)(lane & 15) * 144u + (uint32_t)((lane >> 4) * 16);
    const uint32_t boff = (uint32_t)(lane & 7) * 144u + (uint32_t)(((lane >> 3) & 1) * 16);
    const uint32_t aRow = (uint32_t)(wr * 16) * 144u;

    // ========== GEMM1: 64 x 320 x 768, K=32 chunks, cp.async pipelined ==========
    float acc[20][4];
    #pragma unroll
    for (int j = 0; j < 20; j++) { acc[j][0]=0.f; acc[j][1]=0.f; acc[j][2]=0.f; acc[j][3]=0.f; }

    // per-thread A mapping: row = tid>>2, c16 = tid&3 (8 floats per chunk)
    const int arow = tid >> 2, ac16 = tid & 3;
    const float* zp = z + (size_t)(m0 + arow) * 768 + ac16 * 8;
    const uint32_t aSts = off32((uint32_t)arow, (uint32_t)ac16);
    // per-thread B mapping: 5 units
    uint32_t bdst[5]; int bsrc[5];
    #pragma unroll
    for (int it = 0; it < 5; it++) {
        int u = tid + it * 256, row = u >> 2, c16 = u & 3;
        bdst[it] = off32((uint32_t)row, (uint32_t)c16);
        bsrc[it] = row * 768 + c16 * 8;
    }
    // prologue: B chunk0 -> buf0 ; A chunk0 -> regs
    #pragma unroll
    for (int it = 0; it < 5; it++) {
        CP16(sb + G1_B(0)  + bdst[it], g_Wch + bsrc[it]);
        CP16(sb + G1_BL(0) + bdst[it], g_Wcl + bsrc[it]);
    }
    CPCOMMIT();
    float4 a0 = *(const float4*)(zp);
    float4 a1 = *(const float4*)(zp + 4);

    for (int ch = 0; ch < 24; ch++) {
        const int cur = ch & 1;
        // convert A(ch) into buf cur
        {
            uint32_t h0,l0,h1,l1,h2,l2,h3,l3;
            split2(a0.x, a0.y, h0, l0); split2(a0.z, a0.w, h1, l1);
            split2(a1.x, a1.y, h2, l2); split2(a1.z, a1.w, h3, l3);
            *(uint4*)(sm + G1_A(cur)  + aSts) = make_uint4(h0, h1, h2, h3);
            *(uint4*)(sm + G1_AL(cur) + aSts) = make_uint4(l0, l1, l2, l3);
        }
        // prefetch A(ch+1)
        float4 n0, n1;
        if (ch < 23) { n0 = *(const float4*)(zp + (ch + 1) * 32); n1 = *(const float4*)(zp + (ch + 1) * 32 + 4); }
        CPWAIT0();
        __syncthreads();
        // issue B(ch+1) into other buffer
        if (ch < 23) {
            const int kk = (ch + 1) * 32, nb = cur ^ 1;
            #pragma unroll
            for (int it = 0; it < 5; it++) {
                CP16(sb + G1_B(nb)  + bdst[it], g_Wch + bsrc[it] + kk);
                CP16(sb + G1_BL(nb) + bdst[it], g_Wcl + bsrc[it] + kk);
            }
            CPCOMMIT();
        }
        // MMA on buf cur
        const uint32_t Ah = sb + G1_A(cur), Al = sb + G1_AL(cur);
        const uint32_t Bh = sb + G1_B(cur), Bl = sb + G1_BL(cur);
        #pragma unroll
        for (int ks = 0; ks < 2; ks++) {
            uint32_t ah[4], al[4];
            const uint32_t ao = off32((uint32_t)(wr * 16 + (lane & 15)), (uint32_t)(ks * 2 + (lane >> 4)));
            LDSM4(ah, Ah + ao);
            LDSM4(al, Al + ao);
            #pragma unroll
            for (int j = 0; j < 20; j++) {
                const uint32_t bo = off32((uint32_t)(wc * 160 + j * 8 + (lane & 7)),
                                          (uint32_t)(ks * 2 + ((lane >> 3) & 1)));
                uint32_t bh[2], bl[2];
                LDSM2(bh, Bh + bo);
                LDSM2(bl, Bl + bo);
                MMA16816(acc[j], ah, bh);
                MMA16816(acc[j], al, bh);
                MMA16816(acc[j], ah, bl);
            }
        }
        a0 = n0; a1 = n1;
    }
    __syncthreads();   // GEMM1 buffers dead; float regions live

    // scatter acc -> hs (+b1) / rs (+br)
    #pragma unroll
    for (int j = 0; j < 20; j++) {
        int col = wc * 160 + j * 8 + tig * 2;
        int r0 = wr * 16 + g, r1 = r0 + 8;
        #pragma unroll
        for (int e = 0; e < 2; e++) {
            int c = col + e;
            float v0 = acc[j][e], v1 = acc[j][2 + e];
            if (c < 256) {
                hs[r0 * 257 + c] = v0 + __ldg(&b1[c]);
                hs[r1 * 257 + c] = v1 + __ldg(&b1[c]);
            } else {
                rs[r0 * 65 + c - 256] = v0 + __ldg(&br[c - 256]);
                rs[r1 * 65 + c - 256] = v1 + __ldg(&br[c - 256]);
            }
        }
    }
    __syncthreads();

    // ========== LayerNorm + exact GELU ==========
    for (int rr = wid; rr < 64; rr += 8) {
        float v[8], s = 0.f, s2 = 0.f;
        #pragma unroll
        for (int j = 0; j < 8; j++) {
            float x = hs[rr * 257 + lane + 32 * j];
            v[j] = x; s += x; s2 += x * x;
        }
        #pragma unroll
        for (int o = 16; o > 0; o >>= 1) {
            s  += __shfl_xor_sync(~0u, s,  o);
            s2 += __shfl_xor_sync(~0u, s2, o);
        }
        float mean = s * (1.f / 256.f);
        float rstd = rsqrtf(s2 * (1.f / 256.f) - mean * mean + 1e-5f);
        #pragma unroll
        for (int j = 0; j < 8; j++) {
            int c = lane + 32 * j;
            float y = (v[j] - mean) * rstd * __ldg(&lng[c]) + __ldg(&lnb[c]);
            hs[rr * 257 + c] = 0.5f * y * (1.0f + erff(y * 0.70710678118654752f));
        }
    }
    __syncthreads();

    // ========== W2 GEMM: 64 x 64 x 256 ==========
    float acc2[4][4];
    #pragma unroll
    for (int j = 0; j < 4; j++) { acc2[j][0]=0.f; acc2[j][1]=0.f; acc2[j][2]=0.f; acc2[j][3]=0.f; }
    for (int c2 = 0; c2 < 4; c2++) {
        const int kk2 = c2 * 64;
        #pragma unroll
        for (int it = 0; it < 8; it++) {
            int p = tid + it * 256, row = p >> 5, cp = p & 31;
            uint32_t h01, l01;
            split2(hs[row * 257 + kk2 + 2 * cp], hs[row * 257 + kk2 + 2 * cp + 1], h01, l01);
            uint32_t off = (uint32_t)row * 144u + (uint32_t)cp * 4u;
            *(uint32_t*)(sm + OA2_H + off) = h01;
            *(uint32_t*)(sm + OA2_L + off) = l01;
        }
        #pragma unroll
        for (int it = 0; it < 2; it++) {
            int p = tid + it * 256, row = p >> 3, c = p & 7;
            size_t si = (size_t)row * 256 + kk2 + c * 8;
            uint32_t off = (uint32_t)row * 144u + (uint32_t)c * 16u;
            *(uint4*)(sm + OB2_H + off) = *(const uint4*)(g_W2h + si);
            *(uint4*)(sm + OB2_L + off) = *(const uint4*)(g_W2l + si);
        }
        __syncthreads();
        #pragma unroll
        for (int ks = 0; ks < 4; ks++) {
            const uint32_t ka = (uint32_t)ks * 32u;
            uint32_t ah[4], al[4];
            LDSM4(ah, sb + OA2_H + aRow + aoff + ka);
            LDSM4(al, sb + OA2_L + aRow + aoff + ka);
            #pragma unroll
            for (int j = 0; j < 4; j++) {
                uint32_t bo = (uint32_t)(wc * 32 + j * 8) * 144u + boff + ka;
                uint32_t bh[2], bl[2];
                LDSM2(bh, sb + OB2_H + bo);
                LDSM2(bl, sb + OB2_L + bo);
                MMA16816(acc2[j], ah, bh);
                MMA16816(acc2[j], al, bh);
                MMA16816(acc2[j], ah, bl);
            }
        }
        __syncthreads();
    }
    // hl = acc2 + b2 + rs
    #pragma unroll
    for (int j = 0; j < 4; j++) {
        int col = wc * 32 + j * 8 + tig * 2;
        int r0 = wr * 16 + g, r1 = r0 + 8;
        #pragma unroll
        for (int e = 0; e < 2; e++) {
            int c = col + e;
            hl[r0 * 65 + c] = acc2[j][e]     + __ldg(&b2[c]) + rs[r0 * 65 + c];
            hl[r1 * 65 + c] = acc2[j][2 + e] + __ldg(&b2[c]) + rs[r1 * 65 + c];
        }
    }
    __syncthreads();

    // ========== Wo GEMM: os = hl @ Wo^T (tensor, K=64) ==========
    #pragma unroll
    for (int it = 0; it < 8; it++) {
        int p = tid + it * 256, row = p >> 5, cp = p & 31;
        uint32_t h01, l01;
        split2(hl[row * 65 + 2 * cp], hl[row * 65 + 2 * cp + 1], h01, l01);
        uint32_t off = (uint32_t)row * 144u + (uint32_t)cp * 4u;
        *(uint32_t*)(sm + OA2_H + off) = h01;
        *(uint32_t*)(sm + OA2_L + off) = l01;
    }
    #pragma unroll
    for (int it = 0; it < 2; it++) {
        int p = tid + it * 256, row = p >> 3, c = p & 7;
        size_t si = (size_t)row * 64 + c * 8;
        uint32_t off = (uint32_t)row * 144u + (uint32_t)c * 16u;
        *(uint4*)(sm + OB2_H + off) = *(const uint4*)(g_Woh + si);
        *(uint4*)(sm + OB2_L + off) = *(const uint4*)(g_Wol + si);
    }
    __syncthreads();
    float acc3[4][4];
    #pragma unroll
    for (int j = 0; j < 4; j++) { acc3[j][0]=0.f; acc3[j][1]=0.f; acc3[j][2]=0.f; acc3[j][3]=0.f; }
    #pragma unroll
    for (int ks = 0; ks < 4; ks++) {
        const uint32_t ka = (uint32_t)ks * 32u;
        uint32_t ah[4], al[4];
        LDSM4(ah, sb + OA2_H + aRow + aoff + ka);
        LDSM4(al, sb + OA2_L + aRow + aoff + ka);
        #pragma unroll
        for (int j = 0; j < 4; j++) {
            uint32_t bo = (uint32_t)(wc * 32 + j * 8) * 144u + boff + ka;
            uint32_t bh[2], bl[2];
            LDSM2(bh, sb + OB2_H + bo);
            LDSM2(bl, sb + OB2_L + bo);
            MMA16816(acc3[j], ah, bh);
            MMA16816(acc3[j], al, bh);
            MMA16816(acc3[j], ah, bl);
        }
    }
    __syncthreads();   // all Wo ldsm done before Xt overwrites OA2

    // os + Xt (transposed bf16 hi/lo tiles at OA2, stride 144)
    #pragma unroll
    for (int j = 0; j < 4; j++) {
        int col = wc * 32 + j * 8 + tig * 2;
        int r0 = wr * 16 + g, r1 = r0 + 8;
        #pragma unroll
        for (int e = 0; e < 2; e++) {
            int c = col + e;
            float v0 = acc3[j][e], v1 = acc3[j][2 + e];
            os[r0 * 65 + c] = v0;
            os[r1 * 65 + c] = v1;
            __nv_bfloat16 hb0 = __float2bfloat16(v0);
            __nv_bfloat16 hb1 = __float2bfloat16(v1);
            *(__nv_bfloat16*)(sm + OA2_H + c * 144 + r0 * 2) = hb0;
            *(__nv_bfloat16*)(sm + OA2_H + c * 144 + r1 * 2) = hb1;
            *(__nv_bfloat16*)(sm + OA2_L + c * 144 + r0 * 2) = __float2bfloat16(v0 - __bfloat162float(hb0));
            *(__nv_bfloat16*)(sm + OA2_L + c * 144 + r1 * 2) = __float2bfloat16(v1 - __bfloat162float(hb1));
        }
    }
    __syncthreads();

    // ========== cov MMA: pcov = X^T X via Xt tiles ==========
    float acc4[4][4];
    #pragma unroll
    for (int j = 0; j < 4; j++) { acc4[j][0]=0.f; acc4[j][1]=0.f; acc4[j][2]=0.f; acc4[j][3]=0.f; }
    #pragma unroll
    for (int ks = 0; ks < 4; ks++) {
        const uint32_t ka = (uint32_t)ks * 32u;
        uint32_t ah[4], al[4];
        LDSM4(ah, sb + OA2_H + aRow + aoff + ka);
        LDSM4(al, sb + OA2_L + aRow + aoff + ka);
        #pragma unroll
        for (int j = 0; j < 4; j++) {
            uint32_t bo = (uint32_t)(wc * 32 + j * 8) * 144u + boff + ka;
            uint32_t bh[2], bl[2];
            LDSM2(bh, sb + OA2_H + bo);
            LDSM2(bl, sb + OA2_L + bo);
            MMA16816(acc4[j], ah, bh);
            MMA16816(acc4[j], al, bh);
            MMA16816(acc4[j], ah, bl);
        }
    }
    {
        float* pc = g_pcov + (size_t)blockIdx.x * 4096;
        int j1a = wr * 16 + g, j1b = j1a + 8;
        #pragma unroll
        for (int j = 0; j < 4; j++) {
            int j2 = wc * 32 + j * 8 + tig * 2;
            *(float2*)(pc + j1a * 64 + j2) = make_float2(acc4[j][0], acc4[j][1]);
            *(float2*)(pc + j1b * 64 + j2) = make_float2(acc4[j][2], acc4[j][3]);
        }
    }

    // ========== X + psum ==========
    for (int i = tid; i < 4096; i += 256) {
        int row = i >> 6, j = i & 63;
        g_X[(size_t)(m0 + row) * 64 + j] = os[row * 65 + j];
    }
    if (tid < 64) {
        float s = 0.f;
        #pragma unroll 8
        for (int rr = 0; rr < 64; rr++) s += os[rr * 65 + tid];
        g_psum[blockIdx.x * 64 + tid] = s;
    }
}

__global__ void k_red() {
    int gt = blockIdx.x * 256 + threadIdx.x;
    int e = gt & 4095, ch = gt >> 12;
    const float* p = g_pcov + (size_t)ch * 64 * 4096 + e;
    float s = 0.f;
    #pragma unroll 8
    for (int b = 0; b < 64; b++) s += p[(size_t)b * 4096];
    g_pcov2[ch * 4096 + e] = s;
}

// 1024 threads; matrices stride 68 floats; float4 row-dots (Ss/Wp ~symmetric)
__global__ void k2_ns(const float* __restrict__ Wv, const float* __restrict__ bv,
                      const float* __restrict__ Wm, const float* __restrict__ bm)
{
    float* smf = (float*)dsm;
    float* Ss = smf;            // [64][68]
    float* Wp = smf + 4352;
    float* T1 = smf + 8704;
    float* T2 = smf + 13056;
    __shared__ float mu[64]; __shared__ float sn_s;
    const int tid = threadIdx.x;
    const float Bf = (float)BTOT;
    const int j = tid & 63, rb = (tid >> 6) * 4;   // 4 rows per thread

    // mu (partials into T1 flat[1024])
    {
        int col = tid & 63, q = tid >> 6;
        float s = 0.f;
        for (int b = q; b < NBLK; b += 16) s += g_psum[b * 64 + col];
        T1[q * 64 + col] = s;
        __syncthreads();
        if (tid < 64) {
            float t = 0.f;
            #pragma unroll
            for (int q2 = 0; q2 < 16; q2++) t += T1[q2 * 64 + tid];
            mu[tid] = t / Bf;
        }
        __syncthreads();
    }
    // sigma -> T2
    for (int i = tid; i < 4096; i += 1024) {
        int j1 = i >> 6, j2 = i & 63; float c = 0.f;
        #pragma unroll 8
        for (int ch = 0; ch < 32; ch++) c += g_pcov2[ch * 4096 + i];
        float sig = (c - Bf * mu[j1] * mu[j2]) / (Bf - 1.0f);
        if (j1 == j2) sig += 0.001f;
        T2[j1 * 68 + j2] = sig;
    }
    __syncthreads();
    if (tid < 32) {
        float t = T2[tid * 68 + tid] + T2[(tid + 32) * 68 + tid + 32];
        #pragma unroll
        for (int o = 16; o > 0; o >>= 1) t += __shfl_xor_sync(~0u, t, o);
        if (tid == 0) sn_s = t * 1.5f + 1e-6f;
    }
    __syncthreads();
    float sn = sn_s;
    for (int i = tid; i < 4096; i += 1024) {
        int j1 = i >> 6, j2 = i & 63;
        Ss[j1 * 68 + j2] = T2[j1 * 68 + j2] / sn;
        Wp[j1 * 68 + j2] = (j1 == j2) ? 1.f : 0.f;
    }
    __syncthreads();

    for (int it = 0; it < 5; it++) {
        // T1 = Wp @ Ss   (Ss symmetric: col j = row j)
        {
            float s0=0,s1=0,s2=0,s3=0;
            #pragma unroll
            for (int k4 = 0; k4 < 16; k4++) {
                float4 bb = *(float4*)&Ss[j * 68 + k4 * 4];
                float4 a0 = *(float4*)&Wp[(rb+0) * 68 + k4 * 4];
                float4 a1 = *(float4*)&Wp[(rb+1) * 68 + k4 * 4];
                float4 a2 = *(float4*)&Wp[(rb+2) * 68 + k4 * 4];
                float4 a3 = *(float4*)&Wp[(rb+3) * 68 + k4 * 4];
                s0 += a0.x*bb.x + a0.y*bb.y + a0.z*bb.z + a0.w*bb.w;
                s1 += a1.x*bb.x + a1.y*bb.y + a1.z*bb.z + a1.w*bb.w;
                s2 += a2.x*bb.x + a2.y*bb.y + a2.z*bb.z + a2.w*bb.w;
                s3 += a3.x*bb.x + a3.y*bb.y + a3.z*bb.z + a3.w*bb.w;
            }
            T1[(rb+0)*68+j]=s0; T1[(rb+1)*68+j]=s1; T1[(rb+2)*68+j]=s2; T1[(rb+3)*68+j]=s3;
        }
        __syncthreads();
        // T2 = T1 @ Wp^T  (row j of Wp)
        {
            float s0=0,s1=0,s2=0,s3=0;
            #pragma unroll
            for (int k4 = 0; k4 < 16; k4++) {
                float4 bb = *(float4*)&Wp[j * 68 + k4 * 4];
                float4 a0 = *(float4*)&T1[(rb+0) * 68 + k4 * 4];
                float4 a1 = *(float4*)&T1[(rb+1) * 68 + k4 * 4];
                float4 a2 = *(float4*)&T1[(rb+2) * 68 + k4 * 4];
                float4 a3 = *(float4*)&T1[(rb+3) * 68 + k4 * 4];
                s0 += a0.x*bb.x + a0.y*bb.y + a0.z*bb.z + a0.w*bb.w;
                s1 += a1.x*bb.x + a1.y*bb.y + a1.z*bb.z + a1.w*bb.w;
                s2 += a2.x*bb.x + a2.y*bb.y + a2.z*bb.z + a2.w*bb.w;
                s3 += a3.x*bb.x + a3.y*bb.y + a3.z*bb.z + a3.w*bb.w;
            }
            __syncthreads();
            T2[(rb+0)*68+j]=s0; T2[(rb+1)*68+j]=s1; T2[(rb+2)*68+j]=s2; T2[(rb+3)*68+j]=s3;
        }
        __syncthreads();
        // T1 = 1.5 Wp - 0.5 (T2 @ Wp)   (Wp symmetric: col j = row j)
        {
            float s0=0,s1=0,s2=0,s3=0;
            #pragma unroll
            for (int k4 = 0; k4 < 16; k4++) {
                float4 bb = *(float4*)&Wp[j * 68 + k4 * 4];
                float4 a0 = *(float4*)&T2[(rb+0) * 68 + k4 * 4];
                float4 a1 = *(float4*)&T2[(rb+1) * 68 + k4 * 4];
                float4 a2 = *(float4*)&T2[(rb+2) * 68 + k4 * 4];
                float4 a3 = *(float4*)&T2[(rb+3) * 68 + k4 * 4];
                s0 += a0.x*bb.x + a0.y*bb.y + a0.z*bb.z + a0.w*bb.w;
                s1 += a1.x*bb.x + a1.y*bb.y + a1.z*bb.z + a1.w*bb.w;
                s2 += a2.x*bb.x + a2.y*bb.y + a2.z*bb.z + a2.w*bb.w;
                s3 += a3.x*bb.x + a3.y*bb.y + a3.z*bb.z + a3.w*bb.w;
            }
            T1[(rb+0)*68+j] = 1.5f*Wp[(rb+0)*68+j] - 0.5f*s0;
            T1[(rb+1)*68+j] = 1.5f*Wp[(rb+1)*68+j] - 0.5f*s1;
            T1[(rb+2)*68+j] = 1.5f*Wp[(rb+2)*68+j] - 0.5f*s2;
            T1[(rb+3)*68+j] = 1.5f*Wp[(rb+3)*68+j] - 0.5f*s3;
        }
        __syncthreads();
        for (int i = tid; i < 64 * 68; i += 1024) Wp[i] = T1[i];
        __syncthreads();
    }

    float iss = rsqrtf(sn);
    // Cv/Cm rows; B-row = Wp[kc] (symmetry)
    {
        float sv[4] = {0,0,0,0}, smk[4] = {0,0,0,0};
        #pragma unroll
        for (int k4 = 0; k4 < 16; k4++) {
            float4 bb = *(float4*)&Wp[j * 68 + k4 * 4];   // Wp[kc=j] row
            #pragma unroll
            for (int i = 0; i < 4; i++) {
                float4 av = __ldg((const float4*)(Wv + (rb + i) * 64 + k4 * 4));
                float4 am = __ldg((const float4*)(Wm + (rb + i) * 64 + k4 * 4));
                sv[i]  += av.x*bb.x + av.y*bb.y + av.z*bb.z + av.w*bb.w;
                smk[i] += am.x*bb.x + am.y*bb.y + am.z*bb.z + am.w*bb.w;
            }
        }
        #pragma unroll
        for (int i = 0; i < 4; i++) {
            int jr = rb + i;
            float cv = sv[i] * iss, cm = smk[i] * iss;
            g_Cv[jr * 64 + j] = cv; T1[jr * 68 + j] = cv;
            g_Cm[jr * 64 + j] = cm; T2[jr * 68 + j] = cm;
        }
    }
    __syncthreads();
    if (tid < 64) {
        float s = 0.f, t = 0.f;
        #pragma unroll 8
        for (int k = 0; k < 64; k++) { s += mu[k] * T1[tid * 68 + k]; t += mu[k] * T2[tid * 68 + k]; }
        g_bv2[tid] = bv[tid] - s;
        g_bm2[tid] = bm[tid] - t;
    }
}

// k3: tensor-core epilogue
#define K3_XH 0
#define K3_XL 9216
#define K3_VH 18432
#define K3_VL 27648
#define K3_MH 36864
#define K3_ML 46080
#define SM3   55296
__global__ void __launch_bounds__(256)
k3_out(float* __restrict__ out, const float* __restrict__ scale)
{
    char* sm = dsm;
    const uint32_t sb = smem_u32(sm);
    const int tid = threadIdx.x, wid = tid >> 5, lane = tid & 31;
    const int m0 = blockIdx.x * 64;
    const int wr = wid & 3, wc = wid >> 2;
    const int g = lane >> 2, tig = lane & 3;
    const uint32_t aoff = (uint32_t)(lane & 15) * 144u + (uint32_t)((lane >> 4) * 16);
    const uint32_t boff = (uint32_t)(lane & 7) * 144u + (uint32_t)(((lane >> 3) & 1) * 16);
    const uint32_t aRow = (uint32_t)(wr * 16) * 144u;

    // build tiles: row = tid>>2, quarter q = tid&3 (16 floats each)
    {
        int row = tid >> 2, q = tid & 3;
        const float* xp = g_X + (size_t)(m0 + row) * 64 + q * 16;
        const float* vp = g_Cv + row * 64 + q * 16;
        const float* mp = g_Cm + row * 64 + q * 16;
        uint32_t off = (uint32_t)row * 144u + (uint32_t)q * 32u;
        #pragma unroll
        for (int srcsel = 0; srcsel < 3; srcsel++) {
            const float* p = srcsel == 0 ? xp : (srcsel == 1 ? vp : mp);
            int oh = srcsel == 0 ? K3_XH : (srcsel == 1 ? K3_VH : K3_MH);
            int ol = srcsel == 0 ? K3_XL : (srcsel == 1 ? K3_VL : K3_ML);
            uint32_t h[8], l[8];
            #pragma unroll
            for (int f = 0; f < 4; f++) {
                float4 v = __ldg((const float4*)(p + f * 4));
                split2(v.x, v.y, h[f*2],   l[f*2]);
                split2(v.z, v.w, h[f*2+1], l[f*2+1]);
            }
            *(uint4*)(sm + oh + off)      = make_uint4(h[0], h[1], h[2], h[3]);
            *(uint4*)(sm + oh + off + 16) = make_uint4(h[4], h[5], h[6], h[7]);
            *(uint4*)(sm + ol + off)      = make_uint4(l[0], l[1], l[2], l[3]);
            *(uint4*)(sm + ol + off + 16) = make_uint4(l[4], l[5], l[6], l[7]);
        }
    }
    __syncthreads();

    float av[4][4], am[4][4];
    #pragma unroll
    for (int jj = 0; jj < 4; jj++)
        #pragma unroll
        for (int q = 0; q < 4; q++) { av[jj][q] = 0.f; am[jj][q] = 0.f; }
    #pragma unroll
    for (int ks = 0; ks < 4; ks++) {
        const uint32_t ka = (uint32_t)ks * 32u;
        uint32_t ah[4], al[4];
        LDSM4(ah, sb + K3_XH + aRow + aoff + ka);
        LDSM4(al, sb + K3_XL + aRow + aoff + ka);
        #pragma unroll
        for (int jj = 0; jj < 4; jj++) {
            uint32_t bo = (uint32_t)(wc * 32 + jj * 8) * 144u + boff + ka;
            uint32_t bh[2], bl[2];
            LDSM2(bh, sb + K3_VH + bo);
            LDSM2(bl, sb + K3_VL + bo);
            MMA16816(av[jj], ah, bh);
            MMA16816(av[jj], al, bh);
            MMA16816(av[jj], ah, bl);
            LDSM2(bh, sb + K3_MH + bo);
            LDSM2(bl, sb + K3_ML + bo);
            MMA16816(am[jj], ah, bh);
            MMA16816(am[jj], al, bh);
            MMA16816(am[jj], ah, bl);
        }
    }
    const float sc = __ldg(scale);
    int r0 = wr * 16 + g, r1 = r0 + 8;
    #pragma unroll
    for (int jj = 0; jj < 4; jj++) {
        int c = wc * 32 + jj * 8 + tig * 2;
        float bvc0 = __ldg(&g_bv2[c]), bvc1 = __ldg(&g_bv2[c + 1]);
        float bmc0 = __ldg(&g_bm2[c]), bmc1 = __ldg(&g_bm2[c + 1]);
        float o00 = (av[jj][0] + bvc0) * sc / (1.f + expf(-(am[jj][0] + bmc0)));
        float o01 = (av[jj][1] + bvc1) * sc / (1.f + expf(-(am[jj][1] + bmc1)));
        float o10 = (av[jj][2] + bvc0) * sc / (1.f + expf(-(am[jj][2] + bmc0)));
        float o11 = (av[jj][3] + bvc1) * sc / (1.f + expf(-(am[jj][3] + bmc1)));
        *(float2*)(out + (size_t)(m0 + r0) * 64 + c) = make_float2(o00, o01);
        *(float2*)(out + (size_t)(m0 + r1) * 64 + c) = make_float2(o10, o11);
    }
}

extern "C" void kernel_launch(void* const* d_in, const int* in_sizes, int n_in,
                              void* d_out, int out_size)
{
    (void)in_sizes; (void)n_in; (void)out_size;
    const float* z  = (const float*)d_in[0];
    const float* W1 = (const float*)d_in[1];
    const float* b1 = (const float*)d_in[2];
    const float* lg = (const float*)d_in[3];
    const float* lb = (const float*)d_in[4];
    const float* W2 = (const float*)d_in[5];
    const float* b2 = (const float*)d_in[6];
    const float* Wr = (const float*)d_in[7];
    const float* br = (const float*)d_in[8];
    const float* Wo = (const float*)d_in[9];
    const float* Wv = (const float*)d_in[10];
    const float* bv = (const float*)d_in[11];
    const float* Wm = (const float*)d_in[12];
    const float* bm = (const float*)d_in[13];
    const float* sc = (const float*)d_in[14];
    float* out = (float*)d_out;

    cudaFuncSetAttribute(k1_main, cudaFuncAttributeMaxDynamicSharedMemorySize, SM1);
    cudaFuncSetAttribute(k2_ns,  cudaFuncAttributeMaxDynamicSharedMemorySize, 69632);
    cudaFuncSetAttribute(k3_out, cudaFuncAttributeMaxDynamicSharedMemorySize, SM3);

    k0_prep<<<256, 256>>>(W1, Wr, W2, Wo);
    k1_main<<<NBLK, 256, SM1>>>(z, b1, lg, lb, b2, br);
    k_red<<<512, 256>>>();
    k2_ns<<<1, 1024, 69632>>>(Wv, bv, Wm, bm);
    k3_out<<<2048, 256, SM3>>>(out, sc);
}

// round 7
// speedup vs baseline: 4.4882x; 1.3523x over previous
#include <cuda_runtime.h>
#include <cuda_fp16.h>
#include <math.h>
#include <stdint.h>

#define BTOT 131072
#define NBLK 2048            // BTOT / 64 rows per CTA

extern __shared__ char dsm[];

// ---------- helpers ----------
__device__ __forceinline__ uint32_t smem_u32(const void* p) {
    uint32_t a;
    asm("{ .reg .u64 t; cvta.to.shared.u64 t, %1; cvt.u32.u64 %0, t; }" : "=r"(a) : "l"(p));
    return a;
}
#define LDSM4(r,a) asm volatile("ldmatrix.sync.aligned.m8n8.x4.shared.b16 {%0,%1,%2,%3},[%4];" \
    : "=r"((r)[0]),"=r"((r)[1]),"=r"((r)[2]),"=r"((r)[3]) : "r"(a))
#define MMAF16(c,a,b) asm volatile( \
    "mma.sync.aligned.m16n8k16.row.col.f32.f16.f16.f32 {%0,%1,%2,%3},{%4,%5,%6,%7},{%8,%9},{%0,%1,%2,%3};" \
    : "+f"((c)[0]),"+f"((c)[1]),"+f"((c)[2]),"+f"((c)[3]) \
    : "r"((a)[0]),"r"((a)[1]),"r"((a)[2]),"r"((a)[3]),"r"((b)[0]),"r"((b)[1]))
#define CP16(dst,src) asm volatile("cp.async.cg.shared.global [%0], [%1], 16;" ::"r"(dst),"l"(src))
#define CPCOMMIT()    asm volatile("cp.async.commit_group;" ::: "memory")
#define CPWAIT0()     asm volatile("cp.async.wait_group 0;" ::: "memory")

__device__ __forceinline__ void split2h(float x0, float x1, uint32_t& h, uint32_t& l) {
    __half h0 = __float2half_rn(x0), h1 = __float2half_rn(x1);
    h = (uint32_t)__half_as_ushort(h0) | ((uint32_t)__half_as_ushort(h1) << 16);
    __half l0 = __float2half_rn(x0 - __half2float(h0));
    __half l1 = __float2half_rn(x1 - __half2float(h1));
    l = (uint32_t)__half_as_ushort(l0) | ((uint32_t)__half_as_ushort(l1) << 16);
}
// K=32 tile: 64B rows, rotation swizzle -> conflict-free ldmatrix
__device__ __forceinline__ uint32_t off32(uint32_t row, uint32_t c16) {
    return row * 64u + (((c16 + (row >> 1)) & 3u) << 4);
}

// ---------- scratch ----------
__device__ float g_X[(size_t)BTOT * 64];
__device__ float g_psum[NBLK * 64];
__device__ float g_pcov[(size_t)NBLK * 4096];
__device__ float g_pcov2[32 * 4096];
__device__ float g_Cv[4096], g_Cm[4096], g_bv2[64], g_bm2[64];
__device__ __align__(16) __half g_Wc[320 * 768];
__device__ __align__(16) __half g_W2[64 * 256];
__device__ __align__(16) __half g_Wo[64 * 64];

// k1 smem layout (bytes)
#define G1_A(buf)  ((buf) * 8192)
#define G1_AL(buf) ((buf) * 8192 + 4096)
#define G1_B(buf)  (16384 + (buf) * 20480)   // single fp16 B, 2 bufs -> ends 57344
// float regions (alias GEMM1 tiles after GEMM1 done)
#define F_HS 0               // hs [64][257] floats
#define F_RS 16448           // float index
#define F_HL 20608           // float index  (bytes end 99072)
// 144-stride tiles
#define OA2_H 99072
#define OA2_L 108288
#define OB2   117504
#define SM1   126720

__global__ void k0_prep(const float* __restrict__ W1, const float* __restrict__ Wr,
                        const float* __restrict__ W2, const float* __restrict__ Wo) {
    int gt = blockIdx.x * 256 + threadIdx.x, np = gridDim.x * 256;
    for (int i = gt; i < 320 * 768; i += np) {
        int r = i / 768, c = i - r * 768;
        float v = (r < 256) ? W1[r * 768 + c] : Wr[(r - 256) * 768 + c];
        g_Wc[i] = __float2half_rn(v);
    }
    for (int i = gt; i < 64 * 256; i += np) g_W2[i] = __float2half_rn(W2[i]);
    for (int i = gt; i < 4096; i += np)     g_Wo[i] = __float2half_rn(Wo[i]);
}

__global__ void __launch_bounds__(256, 1)
k1_main(const float* __restrict__ z,  const float* __restrict__ b1,
        const float* __restrict__ lng, const float* __restrict__ lnb,
        const float* __restrict__ b2,  const float* __restrict__ br)
{
    char* sm = dsm;
    const uint32_t sb = smem_u32(sm);
    float* smf = (float*)sm;
    float* hs = smf + F_HS;      // [64][257]
    float* rs = smf + F_RS;      // [64][65]
    float* hl = smf + F_HL;      // [64][65]
    float* os = smf + F_HS;      // [64][65], aliases hs

    const int tid = threadIdx.x, wid = tid >> 5, lane = tid & 31;
    const int m0 = blockIdx.x * 64;
    const int wr = wid & 3, wc = wid >> 2;          // 4 x 2 warp grid
    const int g = lane >> 2, tig = lane & 3;

    // 144-stride lane offsets
    const uint32_t aoff  = (uint32_t)(lane & 15) * 144u + (uint32_t)((lane >> 4) * 16);
    const uint32_t boff4 = (uint32_t)(((lane >> 4) & 1) * 8 + (lane & 7)) * 144u
                         + (uint32_t)(((lane >> 3) & 1) * 16);
    const uint32_t aRow = (uint32_t)(wr * 16) * 144u;
    // off32 B-pair lane decomposition
    const int blocal = ((lane >> 4) & 1) * 8 + (lane & 7);
    const int bhalf  = (lane >> 3) & 1;

    // ========== GEMM1: 64 x 320 x 768, fp16 2-term, cp.async pipelined ==========
    float acc[20][4];
    #pragma unroll
    for (int j = 0; j < 20; j++) { acc[j][0]=0.f; acc[j][1]=0.f; acc[j][2]=0.f; acc[j][3]=0.f; }

    const int arow = tid >> 2, ac16 = tid & 3;
    const float* zp = z + (size_t)(m0 + arow) * 768 + ac16 * 8;
    const uint32_t aSts = off32((uint32_t)arow, (uint32_t)ac16);
    uint32_t bdst[5]; int bsrc[5];
    #pragma unroll
    for (int it = 0; it < 5; it++) {
        int u = tid + it * 256, row = u >> 2, c16 = u & 3;
        bdst[it] = off32((uint32_t)row, (uint32_t)c16);
        bsrc[it] = row * 768 + c16 * 8;
    }
    #pragma unroll
    for (int it = 0; it < 5; it++) CP16(sb + G1_B(0) + bdst[it], g_Wc + bsrc[it]);
    CPCOMMIT();
    float4 a0 = *(const float4*)(zp);
    float4 a1 = *(const float4*)(zp + 4);

    for (int ch = 0; ch < 24; ch++) {
        const int cur = ch & 1;
        {
            uint32_t h0,l0,h1,l1,h2,l2,h3,l3;
            split2h(a0.x, a0.y, h0, l0); split2h(a0.z, a0.w, h1, l1);
            split2h(a1.x, a1.y, h2, l2); split2h(a1.z, a1.w, h3, l3);
            *(uint4*)(sm + G1_A(cur)  + aSts) = make_uint4(h0, h1, h2, h3);
            *(uint4*)(sm + G1_AL(cur) + aSts) = make_uint4(l0, l1, l2, l3);
        }
        float4 n0 = a0, n1 = a1;
        if (ch < 23) { n0 = *(const float4*)(zp + (ch + 1) * 32); n1 = *(const float4*)(zp + (ch + 1) * 32 + 4); }
        CPWAIT0();
        __syncthreads();
        if (ch < 23) {
            const int kk = (ch + 1) * 32, nb = cur ^ 1;
            #pragma unroll
            for (int it = 0; it < 5; it++) CP16(sb + G1_B(nb) + bdst[it], g_Wc + bsrc[it] + kk);
            CPCOMMIT();
        }
        const uint32_t Ah = sb + G1_A(cur), Al = sb + G1_AL(cur), Bh = sb + G1_B(cur);
        #pragma unroll
        for (int ks = 0; ks < 2; ks++) {
            uint32_t ah[4], al[4];
            const uint32_t ao = off32((uint32_t)(wr * 16 + (lane & 15)), (uint32_t)(ks * 2 + (lane >> 4)));
            LDSM4(ah, Ah + ao);
            LDSM4(al, Al + ao);
            #pragma unroll
            for (int p = 0; p < 10; p++) {
                uint32_t bb[4];
                const uint32_t bo = off32((uint32_t)(wc * 160 + p * 16 + blocal), (uint32_t)(ks * 2 + bhalf));
                LDSM4(bb, Bh + bo);
                MMAF16(acc[2*p],   ah, bb);
                MMAF16(acc[2*p],   al, bb);
                MMAF16(acc[2*p+1], ah, bb + 2);
                MMAF16(acc[2*p+1], al, bb + 2);
            }
        }
        a0 = n0; a1 = n1;
    }
    __syncthreads();

    // scatter acc -> hs (+b1) / rs (+br)
    #pragma unroll
    for (int j = 0; j < 20; j++) {
        int col = wc * 160 + j * 8 + tig * 2;
        int r0 = wr * 16 + g, r1 = r0 + 8;
        #pragma unroll
        for (int e = 0; e < 2; e++) {
            int c = col + e;
            float v0 = acc[j][e], v1 = acc[j][2 + e];
            if (c < 256) {
                hs[r0 * 257 + c] = v0 + __ldg(&b1[c]);
                hs[r1 * 257 + c] = v1 + __ldg(&b1[c]);
            } else {
                rs[r0 * 65 + c - 256] = v0 + __ldg(&br[c - 256]);
                rs[r1 * 65 + c - 256] = v1 + __ldg(&br[c - 256]);
            }
        }
    }
    __syncthreads();

    // ========== LayerNorm + exact GELU ==========
    for (int rr = wid; rr < 64; rr += 8) {
        float v[8], s = 0.f, s2 = 0.f;
        #pragma unroll
        for (int j = 0; j < 8; j++) {
            float x = hs[rr * 257 + lane + 32 * j];
            v[j] = x; s += x; s2 += x * x;
        }
        #pragma unroll
        for (int o = 16; o > 0; o >>= 1) {
            s  += __shfl_xor_sync(~0u, s,  o);
            s2 += __shfl_xor_sync(~0u, s2, o);
        }
        float mean = s * (1.f / 256.f);
        float rstd = rsqrtf(s2 * (1.f / 256.f) - mean * mean + 1e-5f);
        #pragma unroll
        for (int j = 0; j < 8; j++) {
            int c = lane + 32 * j;
            float y = (v[j] - mean) * rstd * __ldg(&lng[c]) + __ldg(&lnb[c]);
            hs[rr * 257 + c] = 0.5f * y * (1.0f + erff(y * 0.70710678118654752f));
        }
    }
    __syncthreads();

    // ========== W2 GEMM: 64 x 64 x 256 (fp16 2-term) ==========
    float acc2[4][4];
    #pragma unroll
    for (int j = 0; j < 4; j++) { acc2[j][0]=0.f; acc2[j][1]=0.f; acc2[j][2]=0.f; acc2[j][3]=0.f; }
    for (int c2 = 0; c2 < 4; c2++) {
        const int kk2 = c2 * 64;
        #pragma unroll
        for (int it = 0; it < 8; it++) {
            int p = tid + it * 256, row = p >> 5, cp = p & 31;
            uint32_t h01, l01;
            split2h(hs[row * 257 + kk2 + 2 * cp], hs[row * 257 + kk2 + 2 * cp + 1], h01, l01);
            uint32_t off = (uint32_t)row * 144u + (uint32_t)cp * 4u;
            *(uint32_t*)(sm + OA2_H + off) = h01;
            *(uint32_t*)(sm + OA2_L + off) = l01;
        }
        #pragma unroll
        for (int it = 0; it < 2; it++) {
            int p = tid + it * 256, row = p >> 3, c = p & 7;
            size_t si = (size_t)row * 256 + kk2 + c * 8;
            *(uint4*)(sm + OB2 + (uint32_t)row * 144u + (uint32_t)c * 16u) = *(const uint4*)(g_W2 + si);
        }
        __syncthreads();
        #pragma unroll
        for (int ks = 0; ks < 4; ks++) {
            const uint32_t ka = (uint32_t)ks * 32u;
            uint32_t ah[4], al[4];
            LDSM4(ah, sb + OA2_H + aRow + aoff + ka);
            LDSM4(al, sb + OA2_L + aRow + aoff + ka);
            #pragma unroll
            for (int p = 0; p < 2; p++) {
                uint32_t bb[4];
                LDSM4(bb, sb + OB2 + (uint32_t)(wc * 32 + p * 16) * 144u + boff4 + ka);
                MMAF16(acc2[2*p],   ah, bb);
                MMAF16(acc2[2*p],   al, bb);
                MMAF16(acc2[2*p+1], ah, bb + 2);
                MMAF16(acc2[2*p+1], al, bb + 2);
            }
        }
        __syncthreads();
    }
    #pragma unroll
    for (int j = 0; j < 4; j++) {
        int col = wc * 32 + j * 8 + tig * 2;
        int r0 = wr * 16 + g, r1 = r0 + 8;
        #pragma unroll
        for (int e = 0; e < 2; e++) {
            int c = col + e;
            hl[r0 * 65 + c] = acc2[j][e]     + __ldg(&b2[c]) + rs[r0 * 65 + c];
            hl[r1 * 65 + c] = acc2[j][2 + e] + __ldg(&b2[c]) + rs[r1 * 65 + c];
        }
    }
    __syncthreads();

    // ========== Wo GEMM: os = hl @ Wo^T ==========
    #pragma unroll
    for (int it = 0; it < 8; it++) {
        int p = tid + it * 256, row = p >> 5, cp = p & 31;
        uint32_t h01, l01;
        split2h(hl[row * 65 + 2 * cp], hl[row * 65 + 2 * cp + 1], h01, l01);
        uint32_t off = (uint32_t)row * 144u + (uint32_t)cp * 4u;
        *(uint32_t*)(sm + OA2_H + off) = h01;
        *(uint32_t*)(sm + OA2_L + off) = l01;
    }
    #pragma unroll
    for (int it = 0; it < 2; it++) {
        int p = tid + it * 256, row = p >> 3, c = p & 7;
        *(uint4*)(sm + OB2 + (uint32_t)row * 144u + (uint32_t)c * 16u) = *(const uint4*)(g_Wo + (size_t)row * 64 + c * 8);
    }
    __syncthreads();
    float acc3[4][4];
    #pragma unroll
    for (int j = 0; j < 4; j++) { acc3[j][0]=0.f; acc3[j][1]=0.f; acc3[j][2]=0.f; acc3[j][3]=0.f; }
    #pragma unroll
    for (int ks = 0; ks < 4; ks++) {
        const uint32_t ka = (uint32_t)ks * 32u;
        uint32_t ah[4], al[4];
        LDSM4(ah, sb + OA2_H + aRow + aoff + ka);
        LDSM4(al, sb + OA2_L + aRow + aoff + ka);
        #pragma unroll
        for (int p = 0; p < 2; p++) {
            uint32_t bb[4];
            LDSM4(bb, sb + OB2 + (uint32_t)(wc * 32 + p * 16) * 144u + boff4 + ka);
            MMAF16(acc3[2*p],   ah, bb);
            MMAF16(acc3[2*p],   al, bb);
            MMAF16(acc3[2*p+1], ah, bb + 2);
            MMAF16(acc3[2*p+1], al, bb + 2);
        }
    }
    __syncthreads();

    // os + Xt (transposed fp16 hi/lo tiles)
    #pragma unroll
    for (int j = 0; j < 4; j++) {
        int col = wc * 32 + j * 8 + tig * 2;
        int r0 = wr * 16 + g, r1 = r0 + 8;
        #pragma unroll
        for (int e = 0; e < 2; e++) {
            int c = col + e;
            float v0 = acc3[j][e], v1 = acc3[j][2 + e];
            os[r0 * 65 + c] = v0;
            os[r1 * 65 + c] = v1;
            __half hb0 = __float2half_rn(v0);
            __half hb1 = __float2half_rn(v1);
            *(__half*)(sm + OA2_H + c * 144 + r0 * 2) = hb0;
            *(__half*)(sm + OA2_H + c * 144 + r1 * 2) = hb1;
            *(__half*)(sm + OA2_L + c * 144 + r0 * 2) = __float2half_rn(v0 - __half2float(hb0));
            *(__half*)(sm + OA2_L + c * 144 + r1 * 2) = __float2half_rn(v1 - __half2float(hb1));
        }
    }
    __syncthreads();

    // ========== cov MMA: pcov = X^T X  ((Xh+Xl)^T Xh) ==========
    float acc4[4][4];
    #pragma unroll
    for (int j = 0; j < 4; j++) { acc4[j][0]=0.f; acc4[j][1]=0.f; acc4[j][2]=0.f; acc4[j][3]=0.f; }
    #pragma unroll
    for (int ks = 0; ks < 4; ks++) {
        const uint32_t ka = (uint32_t)ks * 32u;
        uint32_t ah[4], al[4];
        LDSM4(ah, sb + OA2_H + aRow + aoff + ka);
        LDSM4(al, sb + OA2_L + aRow + aoff + ka);
        #pragma unroll
        for (int p = 0; p < 2; p++) {
            uint32_t bb[4];
            LDSM4(bb, sb + OA2_H + (uint32_t)(wc * 32 + p * 16) * 144u + boff4 + ka);
            MMAF16(acc4[2*p],   ah, bb);
            MMAF16(acc4[2*p],   al, bb);
            MMAF16(acc4[2*p+1], ah, bb + 2);
            MMAF16(acc4[2*p+1], al, bb + 2);
        }
    }
    {
        float* pc = g_pcov + (size_t)blockIdx.x * 4096;
        int j1a = wr * 16 + g, j1b = j1a + 8;
        #pragma unroll
        for (int j = 0; j < 4; j++) {
            int j2 = wc * 32 + j * 8 + tig * 2;
            *(float2*)(pc + j1a * 64 + j2) = make_float2(acc4[j][0], acc4[j][1]);
            *(float2*)(pc + j1b * 64 + j2) = make_float2(acc4[j][2], acc4[j][3]);
        }
    }

    // ========== X + psum ==========
    for (int i = tid; i < 4096; i += 256) {
        int row = i >> 6, j = i & 63;
        g_X[(size_t)(m0 + row) * 64 + j] = os[row * 65 + j];
    }
    if (tid < 64) {
        float s = 0.f;
        #pragma unroll 8
        for (int rr = 0; rr < 64; rr++) s += os[rr * 65 + tid];
        g_psum[blockIdx.x * 64 + tid] = s;
    }
}

__global__ void k_red() {
    int gt = blockIdx.x * 256 + threadIdx.x;
    int e = gt & 4095, ch = gt >> 12;
    const float* p = g_pcov + (size_t)ch * 64 * 4096 + e;
    float s = 0.f;
    #pragma unroll 8
    for (int b = 0; b < 64; b++) s += p[(size_t)b * 4096];
    g_pcov2[ch * 4096 + e] = s;
}

__global__ void k2_ns(const float* __restrict__ Wv, const float* __restrict__ bv,
                      const float* __restrict__ Wm, const float* __restrict__ bm)
{
    float* smf = (float*)dsm;
    float* Ss = smf;            // [64][68]
    float* Wp = smf + 4352;
    float* T1 = smf + 8704;
    float* T2 = smf + 13056;
    __shared__ float mu[64]; __shared__ float sn_s;
    const int tid = threadIdx.x;
    const float Bf = (float)BTOT;
    const int j = tid & 63, rb = (tid >> 6) * 4;
    {
        int col = tid & 63, q = tid >> 6;
        float s = 0.f;
        for (int b = q; b < NBLK; b += 16) s += g_psum[b * 64 + col];
        T1[q * 64 + col] = s;
        __syncthreads();
        if (tid < 64) {
            float t = 0.f;
            #pragma unroll
            for (int q2 = 0; q2 < 16; q2++) t += T1[q2 * 64 + tid];
            mu[tid] = t / Bf;
        }
        __syncthreads();
    }
    for (int i = tid; i < 4096; i += 1024) {
        int j1 = i >> 6, j2 = i & 63; float c = 0.f;
        #pragma unroll 8
        for (int ch = 0; ch < 32; ch++) c += g_pcov2[ch * 4096 + i];
        float sig = (c - Bf * mu[j1] * mu[j2]) / (Bf - 1.0f);
        if (j1 == j2) sig += 0.001f;
        T2[j1 * 68 + j2] = sig;
    }
    __syncthreads();
    if (tid < 32) {
        float t = T2[tid * 68 + tid] + T2[(tid + 32) * 68 + tid + 32];
        #pragma unroll
        for (int o = 16; o > 0; o >>= 1) t += __shfl_xor_sync(~0u, t, o);
        if (tid == 0) sn_s = t * 1.5f + 1e-6f;
    }
    __syncthreads();
    float sn = sn_s;
    for (int i = tid; i < 4096; i += 1024) {
        int j1 = i >> 6, j2 = i & 63;
        Ss[j1 * 68 + j2] = T2[j1 * 68 + j2] / sn;
        Wp[j1 * 68 + j2] = (j1 == j2) ? 1.f : 0.f;
    }
    __syncthreads();
    for (int it = 0; it < 5; it++) {
        {
            float s0=0,s1=0,s2=0,s3=0;
            #pragma unroll
            for (int k4 = 0; k4 < 16; k4++) {
                float4 bb = *(float4*)&Ss[j * 68 + k4 * 4];
                float4 a0 = *(float4*)&Wp[(rb+0) * 68 + k4 * 4];
                float4 a1 = *(float4*)&Wp[(rb+1) * 68 + k4 * 4];
                float4 a2 = *(float4*)&Wp[(rb+2) * 68 + k4 * 4];
                float4 a3 = *(float4*)&Wp[(rb+3) * 68 + k4 * 4];
                s0 += a0.x*bb.x + a0.y*bb.y + a0.z*bb.z + a0.w*bb.w;
                s1 += a1.x*bb.x + a1.y*bb.y + a1.z*bb.z + a1.w*bb.w;
                s2 += a2.x*bb.x + a2.y*bb.y + a2.z*bb.z + a2.w*bb.w;
                s3 += a3.x*bb.x + a3.y*bb.y + a3.z*bb.z + a3.w*bb.w;
            }
            T1[(rb+0)*68+j]=s0; T1[(rb+1)*68+j]=s1; T1[(rb+2)*68+j]=s2; T1[(rb+3)*68+j]=s3;
        }
        __syncthreads();
        {
            float s0=0,s1=0,s2=0,s3=0;
            #pragma unroll
            for (int k4 = 0; k4 < 16; k4++) {
                float4 bb = *(float4*)&Wp[j * 68 + k4 * 4];
                float4 a0 = *(float4*)&T1[(rb+0) * 68 + k4 * 4];
                float4 a1 = *(float4*)&T1[(rb+1) * 68 + k4 * 4];
                float4 a2 = *(float4*)&T1[(rb+2) * 68 + k4 * 4];
                float4 a3 = *(float4*)&T1[(rb+3) * 68 + k4 * 4];
                s0 += a0.x*bb.x + a0.y*bb.y + a0.z*bb.z + a0.w*bb.w;
                s1 += a1.x*bb.x + a1.y*bb.y + a1.z*bb.z + a1.w*bb.w;
                s2 += a2.x*bb.x + a2.y*bb.y + a2.z*bb.z + a2.w*bb.w;
                s3 += a3.x*bb.x + a3.y*bb.y + a3.z*bb.z + a3.w*bb.w;
            }
            __syncthreads();
            T2[(rb+0)*68+j]=s0; T2[(rb+1)*68+j]=s1; T2[(rb+2)*68+j]=s2; T2[(rb+3)*68+j]=s3;
        }
        __syncthreads();
        {
            float s0=0,s1=0,s2=0,s3=0;
            #pragma unroll
            for (int k4 = 0; k4 < 16; k4++) {
                float4 bb = *(float4*)&Wp[j * 68 + k4 * 4];
                float4 a0 = *(float4*)&T2[(rb+0) * 68 + k4 * 4];
                float4 a1 = *(float4*)&T2[(rb+1) * 68 + k4 * 4];
                float4 a2 = *(float4*)&T2[(rb+2) * 68 + k4 * 4];
                float4 a3 = *(float4*)&T2[(rb+3) * 68 + k4 * 4];
                s0 += a0.x*bb.x + a0.y*bb.y + a0.z*bb.z + a0.w*bb.w;
                s1 += a1.x*bb.x + a1.y*bb.y + a1.z*bb.z + a1.w*bb.w;
                s2 += a2.x*bb.x + a2.y*bb.y + a2.z*bb.z + a2.w*bb.w;
                s3 += a3.x*bb.x + a3.y*bb.y + a3.z*bb.z + a3.w*bb.w;
            }
            T1[(rb+0)*68+j] = 1.5f*Wp[(rb+0)*68+j] - 0.5f*s0;
            T1[(rb+1)*68+j] = 1.5f*Wp[(rb+1)*68+j] - 0.5f*s1;
            T1[(rb+2)*68+j] = 1.5f*Wp[(rb+2)*68+j] - 0.5f*s2;
            T1[(rb+3)*68+j] = 1.5f*Wp[(rb+3)*68+j] - 0.5f*s3;
        }
        __syncthreads();
        for (int i = tid; i < 64 * 68; i += 1024) Wp[i] = T1[i];
        __syncthreads();
    }
    float iss = rsqrtf(sn);
    {
        float sv[4] = {0,0,0,0}, smk[4] = {0,0,0,0};
        #pragma unroll
        for (int k4 = 0; k4 < 16; k4++) {
            float4 bb = *(float4*)&Wp[j * 68 + k4 * 4];
            #pragma unroll
            for (int i = 0; i < 4; i++) {
                float4 av = __ldg((const float4*)(Wv + (rb + i) * 64 + k4 * 4));
                float4 am = __ldg((const float4*)(Wm + (rb + i) * 64 + k4 * 4));
                sv[i]  += av.x*bb.x + av.y*bb.y + av.z*bb.z + av.w*bb.w;
                smk[i] += am.x*bb.x + am.y*bb.y + am.z*bb.z + am.w*bb.w;
            }
        }
        #pragma unroll
        for (int i = 0; i < 4; i++) {
            int jr = rb + i;
            float cv = sv[i] * iss, cm = smk[i] * iss;
            g_Cv[jr * 64 + j] = cv; T1[jr * 68 + j] = cv;
            g_Cm[jr * 64 + j] = cm; T2[jr * 68 + j] = cm;
        }
    }
    __syncthreads();
    if (tid < 64) {
        float s = 0.f, t = 0.f;
        #pragma unroll 8
        for (int k = 0; k < 64; k++) { s += mu[k] * T1[tid * 68 + k]; t += mu[k] * T2[tid * 68 + k]; }
        g_bv2[tid] = bv[tid] - s;
        g_bm2[tid] = bm[tid] - t;
    }
}

// k3: tensor epilogue, fp16 2-term (X split, Cv/Cm rounded)
#define K3_XH 0
#define K3_XL 9216
#define K3_VH 18432
#define K3_MH 27648
#define SM3   36864
__global__ void __launch_bounds__(256)
k3_out(float* __restrict__ out, const float* __restrict__ scale)
{
    char* sm = dsm;
    const uint32_t sb = smem_u32(sm);
    const int tid = threadIdx.x, wid = tid >> 5, lane = tid & 31;
    const int m0 = blockIdx.x * 64;
    const int wr = wid & 3, wc = wid >> 2;
    const int g = lane >> 2, tig = lane & 3;
    const uint32_t aoff  = (uint32_t)(lane & 15) * 144u + (uint32_t)((lane >> 4) * 16);
    const uint32_t boff4 = (uint32_t)(((lane >> 4) & 1) * 8 + (lane & 7)) * 144u
                         + (uint32_t)(((lane >> 3) & 1) * 16);
    const uint32_t aRow = (uint32_t)(wr * 16) * 144u;

    {
        int row = tid >> 2, q = tid & 3;
        uint32_t off = (uint32_t)row * 144u + (uint32_t)q * 32u;
        // X: split h/l
        {
            const float* xp = g_X + (size_t)(m0 + row) * 64 + q * 16;
            uint32_t h[8], l[8];
            #pragma unroll
            for (int f = 0; f < 4; f++) {
                float4 v = __ldg((const float4*)(xp + f * 4));
                split2h(v.x, v.y, h[f*2],   l[f*2]);
                split2h(v.z, v.w, h[f*2+1], l[f*2+1]);
            }
            *(uint4*)(sm + K3_XH + off)      = make_uint4(h[0], h[1], h[2], h[3]);
            *(uint4*)(sm + K3_XH + off + 16) = make_uint4(h[4], h[5], h[6], h[7]);
            *(uint4*)(sm + K3_XL + off)      = make_uint4(l[0], l[1], l[2], l[3]);
            *(uint4*)(sm + K3_XL + off + 16) = make_uint4(l[4], l[5], l[6], l[7]);
        }
        // Cv / Cm: rounded fp16 only
        #pragma unroll
        for (int srcsel = 0; srcsel < 2; srcsel++) {
            const float* p = srcsel == 0 ? (g_Cv + row * 64 + q * 16) : (g_Cm + row * 64 + q * 16);
            int oh = srcsel == 0 ? K3_VH : K3_MH;
            uint32_t h[8], l[8];
            #pragma unroll
            for (int f = 0; f < 4; f++) {
                float4 v = __ldg((const float4*)(p + f * 4));
                split2h(v.x, v.y, h[f*2],   l[f*2]);
                split2h(v.z, v.w, h[f*2+1], l[f*2+1]);
            }
            *(uint4*)(sm + oh + off)      = make_uint4(h[0], h[1], h[2], h[3]);
            *(uint4*)(sm + oh + off + 16) = make_uint4(h[4], h[5], h[6], h[7]);
        }
    }
    __syncthreads();

    float av[4][4], am[4][4];
    #pragma unroll
    for (int jj = 0; jj < 4; jj++)
        #pragma unroll
        for (int q = 0; q < 4; q++) { av[jj][q] = 0.f; am[jj][q] = 0.f; }
    #pragma unroll
    for (int ks = 0; ks < 4; ks++) {
        const uint32_t ka = (uint32_t)ks * 32u;
        uint32_t ah[4], al[4];
        LDSM4(ah, sb + K3_XH + aRow + aoff + ka);
        LDSM4(al, sb + K3_XL + aRow + aoff + ka);
        #pragma unroll
        for (int p = 0; p < 2; p++) {
            uint32_t vb[4], mb[4];
            const uint32_t brow = (uint32_t)(wc * 32 + p * 16) * 144u + boff4 + ka;
            LDSM4(vb, sb + K3_VH + brow);
            LDSM4(mb, sb + K3_MH + brow);
            MMAF16(av[2*p],   ah, vb); MMAF16(av[2*p],   al, vb);
            MMAF16(av[2*p+1], ah, vb + 2); MMAF16(av[2*p+1], al, vb + 2);
            MMAF16(am[2*p],   ah, mb); MMAF16(am[2*p],   al, mb);
            MMAF16(am[2*p+1], ah, mb + 2); MMAF16(am[2*p+1], al, mb + 2);
        }
    }
    const float sc = __ldg(scale);
    int r0 = wr * 16 + g, r1 = r0 + 8;
    #pragma unroll
    for (int jj = 0; jj < 4; jj++) {
        int c = wc * 32 + jj * 8 + tig * 2;
        float bvc0 = __ldg(&g_bv2[c]), bvc1 = __ldg(&g_bv2[c + 1]);
        float bmc0 = __ldg(&g_bm2[c]), bmc1 = __ldg(&g_bm2[c + 1]);
        float o00 = (av[jj][0] + bvc0) * sc / (1.f + expf(-(am[jj][0] + bmc0)));
        float o01 = (av[jj][1] + bvc1) * sc / (1.f + expf(-(am[jj][1] + bmc1)));
        float o10 = (av[jj][2] + bvc0) * sc / (1.f + expf(-(am[jj][2] + bmc0)));
        float o11 = (av[jj][3] + bvc1) * sc / (1.f + expf(-(am[jj][3] + bmc1)));
        *(float2*)(out + (size_t)(m0 + r0) * 64 + c) = make_float2(o00, o01);
        *(float2*)(out + (size_t)(m0 + r1) * 64 + c) = make_float2(o10, o11);
    }
}

extern "C" void kernel_launch(void* const* d_in, const int* in_sizes, int n_in,
                              void* d_out, int out_size)
{
    (void)in_sizes; (void)n_in; (void)out_size;
    const float* z  = (const float*)d_in[0];
    const float* W1 = (const float*)d_in[1];
    const float* b1 = (const float*)d_in[2];
    const float* lg = (const float*)d_in[3];
    const float* lb = (const float*)d_in[4];
    const float* W2 = (const float*)d_in[5];
    const float* b2 = (const float*)d_in[6];
    const float* Wr = (const float*)d_in[7];
    const float* br = (const float*)d_in[8];
    const float* Wo = (const float*)d_in[9];
    const float* Wv = (const float*)d_in[10];
    const float* bv = (const float*)d_in[11];
    const float* Wm = (const float*)d_in[12];
    const float* bm = (const float*)d_in[13];
    const float* sc = (const float*)d_in[14];
    float* out = (float*)d_out;

    cudaFuncSetAttribute(k1_main, cudaFuncAttributeMaxDynamicSharedMemorySize, SM1);
    cudaFuncSetAttribute(k2_ns,  cudaFuncAttributeMaxDynamicSharedMemorySize, 69632);
    cudaFuncSetAttribute(k3_out, cudaFuncAttributeMaxDynamicSharedMemorySize, SM3);

    k0_prep<<<256, 256>>>(W1, Wr, W2, Wo);
    k1_main<<<NBLK, 256, SM1>>>(z, b1, lg, lb, b2, br);
    k_red<<<512, 256>>>();
    k2_ns<<<1, 1024, 69632>>>(Wv, bv, Wm, bm);
    k3_out<<<2048, 256, SM3>>>(out, sc);
}